// round 14
// baseline (speedup 1.0000x reference)
#include <cuda_runtime.h>
#include <cuda_bf16.h>
#include <math.h>
#include <stdint.h>
#include <float.h>

#define B_ 16
#define T_ 2048
#define D_ 512
#define H_ 64

typedef unsigned long long u64;

// ---------------- device scratch (no allocations allowed) ----------------
__device__ float4 g_P[B_ * T_];                    // 4-momenta
__device__ int    g_len[B_];                       // valid lengths per batch
__device__ __nv_bfloat16 g_Ahi[B_ * T_ * H_];      // h split hi
__device__ __nv_bfloat16 g_Alo[B_ * T_ * H_];      // h split lo
__device__ __nv_bfloat16 g_Bhi[D_ * H_];           // W2^T split hi  [n][k]
__device__ __nv_bfloat16 g_Blo[D_ * H_];           // W2^T split lo  [n][k]

// ---------------- f32x2 packed helpers ----------------
__device__ __forceinline__ u64 dup2(float a) {
    u64 r; asm("mov.b64 %0, {%1, %1};" : "=l"(r) : "f"(a)); return r;
}
__device__ __forceinline__ float2 unpack2(u64 v) {
    float2 f; asm("mov.b64 {%0, %1}, %2;" : "=f"(f.x), "=f"(f.y) : "l"(v)); return f;
}
__device__ __forceinline__ u64 fma2(u64 a, u64 b, u64 c) {
    u64 d; asm("fma.rn.f32x2 %0, %1, %2, %3;" : "=l"(d) : "l"(a), "l"(b), "l"(c)); return d;
}
__device__ __forceinline__ u64 mul2(u64 a, u64 b) {
    u64 d; asm("mul.rn.f32x2 %0, %1, %2;" : "=l"(d) : "l"(a), "l"(b)); return d;
}
__device__ __forceinline__ float gelu(float x) {
    return 0.5f * x * (1.f + erff(x * 0.70710678118654752f));
}
__device__ __forceinline__ uint32_t smem_u32(const void* p) {
    uint32_t a;
    asm("{ .reg .u64 t; cvta.to.shared.u64 t, %1; cvt.u32.u64 %0, t; }"
        : "=r"(a) : "l"(p));
    return a;
}

// bf16 mma m16n8k16, f32 accum (plain PTX, sm_80+, OK on sm_103 target)
#define MMA16816(d, a, b) \
    asm volatile("mma.sync.aligned.m16n8k16.row.col.f32.bf16.bf16.f32 " \
        "{%0,%1,%2,%3}, {%4,%5,%6,%7}, {%8,%9}, {%0,%1,%2,%3};" \
        : "+f"((d)[0]), "+f"((d)[1]), "+f"((d)[2]), "+f"((d)[3]) \
        : "r"((a)[0]), "r"((a)[1]), "r"((a)[2]), "r"((a)[3]), \
          "r"((b)[0]), "r"((b)[1]))

__device__ __forceinline__ void ldm_x4(uint32_t* r, uint32_t saddr) {
    asm volatile("ldmatrix.sync.aligned.m8n8.x4.shared.b16 {%0,%1,%2,%3}, [%4];"
        : "=r"(r[0]), "=r"(r[1]), "=r"(r[2]), "=r"(r[3]) : "r"(saddr));
}

#define SWZ(o) ((o) ^ (((o) >> 3) & 0x70))

// =========================================================================
// Kernel 0: fused setup (prep / len / w2t by block range).
//   blocks [0,64)    : 4-momenta, 2 tokens/thread for ILP
//   blocks [64,80)   : per-batch valid length
//   blocks [80,208)  : W2^T bf16 hi/lo planes
// =========================================================================
__global__ __launch_bounds__(256) void setup_kernel(
    const float* __restrict__ tokens, const unsigned char* __restrict__ mask,
    const float* __restrict__ W2)
{
    int bid = blockIdx.x;
    int tid = threadIdx.x;

    if (bid < 64) {
        int gt0 = bid * 512 + tid;
        int gt1 = gt0 + 256;
        float4 tk0 = ((const float4*)tokens)[gt0];
        float4 tk1 = ((const float4*)tokens)[gt1];
        float e0 = fminf(fmaxf(tk0.z, -20.f), 20.f);
        float e1 = fminf(fmaxf(tk1.z, -20.f), 20.f);
        float sp0, cp0, sp1, cp1;
        sincosf(tk0.w, &sp0, &cp0);
        sincosf(tk1.w, &sp1, &cp1);
        float sh0 = sinhf(e0);
        float sh1 = sinhf(e1);
        g_P[gt0] = make_float4(tk0.x, tk0.y * cp0, tk0.y * sp0, tk0.y * sh0);
        g_P[gt1] = make_float4(tk1.x, tk1.y * cp1, tk1.y * sp1, tk1.y * sh1);
    } else if (bid < 80) {
        int b = bid - 64;
        unsigned int w0 = *(const unsigned int*)mask;
        bool byteMode = (w0 == 0x01010101u);
        int cnt = 0;
        for (int s = tid; s < T_; s += 256) {
            unsigned int mv = byteMode ? (unsigned int)mask[b * T_ + s]
                                       : ((const unsigned int*)mask)[b * T_ + s];
            cnt += (mv != 0u);
        }
        for (int o = 16; o; o >>= 1) cnt += __shfl_down_sync(0xffffffffu, cnt, o);
        __shared__ int sred[8];
        if ((tid & 31) == 0) sred[tid >> 5] = cnt;
        __syncthreads();
        if (tid == 0) {
            int tot = 0;
#pragma unroll
            for (int i = 0; i < 8; i++) tot += sred[i];
            g_len[b] = tot;
        }
    } else {
        int idx = (bid - 80) * 256 + tid;
        int k = idx >> 9;
        int n = idx & 511;
        float wv = W2[k * D_ + n];
        __nv_bfloat16 h = __float2bfloat16(wv);
        g_Bhi[n * H_ + k] = h;
        g_Blo[n * H_ + k] = __float2bfloat16(wv - __bfloat162float(h));
    }
}

// =========================================================================
// Kernel 2: per-token top-8 Minkowski dot -> masses -> FUSED h (bf16 split).
// Block = 32 tokens (lane<->token), 8 warps scan eighths.
// =========================================================================
#define CEA(a, b) do { float _l = fminf(a, b), _h = fmaxf(a, b); (a) = _l; (b) = _h; } while (0)

#define SORT8A(v0,v1,v2,v3,v4,v5,v6,v7) do {                 \
    CEA(v0, v1); CEA(v2, v3); CEA(v4, v5); CEA(v6, v7);      \
    CEA(v0, v2); CEA(v1, v3); CEA(v4, v6); CEA(v5, v7);      \
    CEA(v1, v2); CEA(v5, v6);                                \
    CEA(v0, v4); CEA(v1, v5); CEA(v2, v6); CEA(v3, v7);      \
    CEA(v2, v4); CEA(v3, v5);                                \
    CEA(v1, v2); CEA(v3, v4); CEA(v5, v6);                   \
} while (0)

#define CLEAN8(m0,m1,m2,m3,m4,m5,m6,m7) do {                 \
    CEA(m0, m4); CEA(m1, m5); CEA(m2, m6); CEA(m3, m7);      \
    CEA(m0, m2); CEA(m1, m3); CEA(m4, m6); CEA(m5, m7);      \
    CEA(m0, m1); CEA(m2, m3); CEA(m4, m5); CEA(m6, m7);      \
} while (0)

#define VINS(dv) do { float c = (dv), t_;                 \
    t_ = fminf(c, th1); c = fmaxf(c, th1); th0 = t_;      \
    t_ = fminf(c, th2); c = fmaxf(c, th2); th1 = t_;      \
    t_ = fminf(c, th3); c = fmaxf(c, th3); th2 = t_;      \
    t_ = fminf(c, th4); c = fmaxf(c, th4); th3 = t_;      \
    t_ = fminf(c, th5); c = fmaxf(c, th5); th4 = t_;      \
    t_ = fminf(c, th6); c = fmaxf(c, th6); th5 = t_;      \
    t_ = fminf(c, th7); c = fmaxf(c, th7); th6 = t_;      \
    th7 = c;                                              \
} while (0)

#define CAPTURE(dv, si) do {                                          \
    float _d = (dv);                                                  \
    if (_d >= th) {                                                   \
        if (_d > th) {                                                \
            if (na < 8) { av[na] = _d; ai[na] = (si); na++; }         \
        } else {                                                      \
            if (nb < 8) { bi[nb] = (si); nb++; }                      \
        }                                                             \
    }                                                                 \
} while (0)

__device__ __forceinline__ void dot8f(
    const float* sE, const float* sX, const float* sY, const float* sZ,
    int s, u64 aE2, u64 ax2, u64 ay2, u64 az2, float* v)
{
    ulonglong2 E01 = *(const ulonglong2*)&sE[s];
    ulonglong2 X01 = *(const ulonglong2*)&sX[s];
    ulonglong2 Y01 = *(const ulonglong2*)&sY[s];
    ulonglong2 Z01 = *(const ulonglong2*)&sZ[s];
    u64 p0 = fma2(aE2, E01.x, fma2(ax2, X01.x, fma2(ay2, Y01.x, mul2(az2, Z01.x))));
    u64 p1 = fma2(aE2, E01.y, fma2(ax2, X01.y, fma2(ay2, Y01.y, mul2(az2, Z01.y))));
    float2 d0 = unpack2(p0), d1 = unpack2(p1);
    v[0] = d0.x; v[1] = d0.y; v[2] = d1.x; v[3] = d1.y;
}

// per-thread h-chunk: token gt (global), hidden [hh, hh+8) from smem W1/b1
__device__ __forceinline__ void emit_h_chunk(
    int gt, int hh, float m0, float m1, float m2,
    const float* sW1s, const float* sb1s)
{
    __align__(16) __nv_bfloat16 hi8[8];
    __align__(16) __nv_bfloat16 lo8[8];
#pragma unroll
    for (int j = 0; j < 8; j++) {
        int k = hh + j;
        float x = fmaf(m0, sW1s[k], fmaf(m1, sW1s[H_ + k],
                  fmaf(m2, sW1s[2 * H_ + k], sb1s[k])));
        float g = gelu(x);
        __nv_bfloat16 h = __float2bfloat16(g);
        hi8[j] = h;
        lo8[j] = __float2bfloat16(g - __bfloat162float(h));
    }
    *(uint4*)&g_Ahi[(size_t)gt * H_ + hh] = *(const uint4*)hi8;
    *(uint4*)&g_Alo[(size_t)gt * H_ + hh] = *(const uint4*)lo8;
}

__global__ __launch_bounds__(256) void mass_kernel(
    const float* __restrict__ W1, const float* __restrict__ b1)
{
    extern __shared__ __align__(16) unsigned char smem_raw[];
    float* sE  = (float*)smem_raw;
    float* sX  = sE + T_;
    float* sY  = sX + T_;
    float* sZ  = sY + T_;
    float* sAv = sZ + T_;
    int*   sAi = (int*)(sAv + 256 * 8);
    int*   sBi = sAi + 256 * 8;
    __shared__ float sM[32 * 3];
    __shared__ float sW1s[3 * H_];
    __shared__ float sb1s[H_];

    int b = blockIdx.y;
    int len = g_len[b];
    int tbase = blockIdx.x * 32;
    int tid = threadIdx.x, lane = tid & 31, w = tid >> 5;
    float mv = sqrtf(1e-8f);

    if (tid < 3 * H_) sW1s[tid] = W1[tid];
    if (tid < H_) sb1s[tid] = b1[tid];

    if (tbase >= len) {                 // whole block masked: constant h
        __syncthreads();
        int tt = tbase + (tid >> 3);
        int hh = (tid & 7) * 8;
        emit_h_chunk(b * T_ + tt, hh, mv, mv, mv, sW1s, sb1s);
        return;
    }

    const float4* gp = g_P + b * T_;
    for (int i = tid; i < T_; i += 256) {
        float4 p = gp[i];
        sE[i] = p.x; sX[i] = p.y; sY[i] = p.z; sZ[i] = p.w;
    }
    __syncthreads();

    int t = tbase + lane;
    int q0 = (w * len) >> 3;
    int q1 = ((w + 1) * len) >> 3;

    float aE = sE[t], ax = -sX[t], ay = -sY[t], az = -sZ[t];
    u64 aE2 = dup2(aE), ax2 = dup2(ax), ay2 = dup2(ay), az2 = dup2(az);

    float th0 = -FLT_MAX, th1 = -FLT_MAX, th2 = -FLT_MAX, th3 = -FLT_MAX;
    float th4 = -FLT_MAX, th5 = -FLT_MAX, th6 = -FLT_MAX, th7 = -FLT_MAX;

    int s0 = (q0 + 3) & ~3; if (s0 > q1) s0 = q1;
    int s1a = s0 + ((q1 - s0) & ~15);

    // ---- pass 1: always-sort batched top-8 (value-multiset exact) ----
    for (int s = q0; s < s0; s++) {
        float d = fmaf(aE, sE[s], fmaf(ax, sX[s], fmaf(ay, sY[s], az * sZ[s])));
        if (d > th0) VINS(d);
    }
    for (int s = s0; s < s1a; s += 16) {
        float v[16];
        dot8f(sE, sX, sY, sZ, s,      aE2, ax2, ay2, az2, v);
        dot8f(sE, sX, sY, sZ, s + 4,  aE2, ax2, ay2, az2, v + 4);
        dot8f(sE, sX, sY, sZ, s + 8,  aE2, ax2, ay2, az2, v + 8);
        dot8f(sE, sX, sY, sZ, s + 12, aE2, ax2, ay2, az2, v + 12);
        SORT8A(v[0], v[1], v[2], v[3], v[4], v[5], v[6], v[7]);
        SORT8A(v[8], v[9], v[10], v[11], v[12], v[13], v[14], v[15]);
        float m0 = fmaxf(v[0], v[15]), m1 = fmaxf(v[1], v[14]);
        float m2 = fmaxf(v[2], v[13]), m3 = fmaxf(v[3], v[12]);
        float m4 = fmaxf(v[4], v[11]), m5 = fmaxf(v[5], v[10]);
        float m6 = fmaxf(v[6], v[9]),  m7 = fmaxf(v[7], v[8]);
        CLEAN8(m0, m1, m2, m3, m4, m5, m6, m7);
        float u0 = fmaxf(th0, m7), u1 = fmaxf(th1, m6);
        float u2 = fmaxf(th2, m5), u3 = fmaxf(th3, m4);
        float u4 = fmaxf(th4, m3), u5 = fmaxf(th5, m2);
        float u6 = fmaxf(th6, m1), u7 = fmaxf(th7, m0);
        CLEAN8(u0, u1, u2, u3, u4, u5, u6, u7);
        th0 = u0; th1 = u1; th2 = u2; th3 = u3;
        th4 = u4; th5 = u5; th6 = u6; th7 = u7;
    }
    for (int s = s1a; s < q1; s++) {
        float d = fmaf(aE, sE[s], fmaf(ax, sX[s], fmaf(ay, sY[s], az * sZ[s])));
        if (d > th0) VINS(d);
    }

    // ---- pass 2: tie-exact index capture in ascending s ----
    float th = th0;
    float* av = &sAv[tid * 8];
    int*   ai = &sAi[tid * 8];
    int*   bi = &sBi[tid * 8];
    int na = 0, nb = 0;

    for (int s = q0; s < s0; s++) {
        float d = fmaf(aE, sE[s], fmaf(ax, sX[s], fmaf(ay, sY[s], az * sZ[s])));
        CAPTURE(d, s);
    }
    for (int s = s0; s < s1a; s += 16) {
        float v[16];
        dot8f(sE, sX, sY, sZ, s,      aE2, ax2, ay2, az2, v);
        dot8f(sE, sX, sY, sZ, s + 4,  aE2, ax2, ay2, az2, v + 4);
        dot8f(sE, sX, sY, sZ, s + 8,  aE2, ax2, ay2, az2, v + 8);
        dot8f(sE, sX, sY, sZ, s + 12, aE2, ax2, ay2, az2, v + 12);
        float g0 = fmaxf(fmaxf(v[0], v[1]), fmaxf(v[2], v[3]));
        float g1 = fmaxf(fmaxf(v[4], v[5]), fmaxf(v[6], v[7]));
        float g2 = fmaxf(fmaxf(v[8], v[9]), fmaxf(v[10], v[11]));
        float g3 = fmaxf(fmaxf(v[12], v[13]), fmaxf(v[14], v[15]));
        if (fmaxf(fmaxf(g0, g1), fmaxf(g2, g3)) >= th) {
#pragma unroll
            for (int k = 0; k < 16; k++) CAPTURE(v[k], s + k);
        }
    }
    for (int s = s1a; s < q1; s++) {
        float d = fmaf(aE, sE[s], fmaf(ax, sX[s], fmaf(ay, sY[s], az * sZ[s])));
        CAPTURE(d, s);
    }

    // ---- build eighth list: stable-desc-sort(A) ++ ties(B asc index) ----
    {
        float v[8]; int idA[8]; int bReg[8];
#pragma unroll
        for (int j = 0; j < 8; j++) {
            v[j]   = (j < na) ? av[j] : -FLT_MAX;
            idA[j] = (j < na) ? ai[j] : 0;
            bReg[j] = bi[j];
        }
#pragma unroll
        for (int i = 0; i < 7; i++) {
#pragma unroll
            for (int j = 0; j < 7 - i; j++) {
                bool p = v[j + 1] > v[j];
                float hv = p ? v[j + 1] : v[j];
                float lv = p ? v[j] : v[j + 1];
                int hi_ = p ? idA[j + 1] : idA[j];
                int lo_ = p ? idA[j] : idA[j + 1];
                v[j] = hv; v[j + 1] = lv; idA[j] = hi_; idA[j + 1] = lo_;
            }
        }
#pragma unroll
        for (int j = 0; j < 8; j++) {
            int jb = j - na; jb = jb < 0 ? 0 : (jb > 7 ? 7 : jb);
            av[j] = (j < na) ? v[j] : th;
            ai[j] = (j < na) ? idA[j] : bReg[jb];
        }
    }
    __syncthreads();

    // ---- warp 0: 8-way merge + cumsum -> masses to smem ----
    if (w == 0) {
        if (t >= len) {
            sM[lane * 3 + 0] = mv; sM[lane * 3 + 1] = mv; sM[lane * 3 + 2] = mv;
        } else {
            float vh[8]; int pp[8];
#pragma unroll
            for (int q = 0; q < 8; q++) { pp[q] = 0; vh[q] = sAv[(q * 32 + lane) * 8]; }
            float cE = 0.f, cX = 0.f, cY = 0.f, cZ = 0.f;
            float m[3]; int kk = 0;
#pragma unroll
            for (int j = 0; j < 8; j++) {
                int bq = 0; float bv = vh[0];
#pragma unroll
                for (int q = 1; q < 8; q++)
                    if (vh[q] > bv) { bv = vh[q]; bq = q; }   // tie -> lower eighth
                int ix = 0;
#pragma unroll
                for (int q = 0; q < 8; q++) {
                    if (bq == q) {
                        ix = sAi[(q * 32 + lane) * 8 + pp[q]];
                        pp[q]++;
                        vh[q] = (pp[q] < 8) ? sAv[(q * 32 + lane) * 8 + pp[q]] : -FLT_MAX;
                    }
                }
                cE += sE[ix]; cX += sX[ix]; cY += sY[ix]; cZ += sZ[ix];
                if (j == 1 || j == 3 || j == 7) {
                    float m2 = fmaf(cE, cE, -fmaf(cX, cX, fmaf(cY, cY, cZ * cZ)));
                    m[kk++] = sqrtf(fmaxf(m2, 0.f) + 1e-8f);
                }
            }
            sM[lane * 3 + 0] = m[0]; sM[lane * 3 + 1] = m[1]; sM[lane * 3 + 2] = m[2];
        }
    }
    __syncthreads();

    // ---- fused h: 256 threads = 32 tokens x 8 hidden-chunks ----
    {
        int tt = tid >> 3;
        int hh = (tid & 7) * 8;
        float m0 = sM[tt * 3 + 0];
        float m1 = sM[tt * 3 + 1];
        float m2 = sM[tt * 3 + 2];
        emit_h_chunk(b * T_ + tbase + tt, hh, m0, m1, m2, sW1s, sb1s);
    }
}

// =========================================================================
// Kernel 3: out = h @ W2 + b2 via mma.sync (split bf16, 3 terms).
// Block = 256 thr (8 warps): 128 tokens x 64 cols; warp = 32 tok x 32 col.
// __launch_bounds__(256,4): cap regs at 64 -> 4 blocks/SM.
// =========================================================================
__global__ __launch_bounds__(256, 4) void mlp_mma(
    const float* __restrict__ b2, float* __restrict__ out)
{
    extern __shared__ __align__(1024) unsigned char sm[];
    unsigned char* sAhi = sm;                  // 128 x 128B = 16K
    unsigned char* sAlo = sm + 16384;          // 16K
    unsigned char* sBhi = sm + 32768;          // 8K
    unsigned char* sBlo = sm + 40960;          // 8K  (total 48K)

    int tid = threadIdx.x, lane = tid & 31, w = tid >> 5;
    int cb = (blockIdx.x & 7) * 64;
    int tok0 = (blockIdx.x >> 3) * 128;
    int wm = w & 3, wn = w >> 2;
    int qid = lane & 3, grp = lane >> 2;
    int rl = lane & 15, cl = lane >> 4;

#pragma unroll
    for (int i = 0; i < 4; i++) {
        int idx = i * 256 + tid;
        int row = idx >> 3, c = idx & 7;
        uint32_t o = SWZ((uint32_t)(row * 128 + c * 16));
        *(uint4*)(sAhi + o) = ((const uint4*)(g_Ahi + (size_t)(tok0 + row) * H_))[c];
        *(uint4*)(sAlo + o) = ((const uint4*)(g_Alo + (size_t)(tok0 + row) * H_))[c];
    }
#pragma unroll
    for (int i = 0; i < 2; i++) {
        int idx = i * 256 + tid;
        int row = idx >> 3, c = idx & 7;
        uint32_t o = SWZ((uint32_t)(row * 128 + c * 16));
        *(uint4*)(sBhi + o) = ((const uint4*)(g_Bhi + (size_t)(cb + row) * H_))[c];
        *(uint4*)(sBlo + o) = ((const uint4*)(g_Blo + (size_t)(cb + row) * H_))[c];
    }
    __syncthreads();

    uint32_t aAhi = smem_u32(sAhi), aAlo = smem_u32(sAlo);
    uint32_t aBhi = smem_u32(sBhi), aBlo = smem_u32(sBlo);

    float acc[2][4][4];
#pragma unroll
    for (int nt = 0; nt < 4; nt++) {
        float2 bv = *(const float2*)&b2[cb + wn * 32 + nt * 8 + qid * 2];
#pragma unroll
        for (int mt = 0; mt < 2; mt++) {
            acc[mt][nt][0] = bv.x; acc[mt][nt][1] = bv.y;
            acc[mt][nt][2] = bv.x; acc[mt][nt][3] = bv.y;
        }
    }

#pragma unroll
    for (int ks = 0; ks < 4; ks++) {
        uint32_t ah[2][4], al[2][4];
#pragma unroll
        for (int mt = 0; mt < 2; mt++) {
            uint32_t o = SWZ((uint32_t)((wm * 32 + mt * 16 + rl) * 128 + (ks * 2 + cl) * 16));
            ldm_x4(ah[mt], aAhi + o);
            ldm_x4(al[mt], aAlo + o);
        }
#pragma unroll
        for (int ntp = 0; ntp < 2; ntp++) {
            uint32_t bh[4], bl[4];
            uint32_t ob = SWZ((uint32_t)((wn * 32 + ntp * 16 + rl) * 128 + (ks * 2 + cl) * 16));
            ldm_x4(bh, aBhi + ob);
            ldm_x4(bl, aBlo + ob);
            uint32_t bfh0[2] = {bh[0], bh[2]}, bfh1[2] = {bh[1], bh[3]};
            uint32_t bfl0[2] = {bl[0], bl[2]}, bfl1[2] = {bl[1], bl[3]};
#pragma unroll
            for (int mt = 0; mt < 2; mt++) {
                MMA16816(acc[mt][ntp * 2],     ah[mt], bfh0);
                MMA16816(acc[mt][ntp * 2],     ah[mt], bfl0);
                MMA16816(acc[mt][ntp * 2],     al[mt], bfh0);
                MMA16816(acc[mt][ntp * 2 + 1], ah[mt], bfh1);
                MMA16816(acc[mt][ntp * 2 + 1], ah[mt], bfl1);
                MMA16816(acc[mt][ntp * 2 + 1], al[mt], bfh1);
            }
        }
    }

#pragma unroll
    for (int mt = 0; mt < 2; mt++) {
        int row = tok0 + wm * 32 + mt * 16 + grp;
#pragma unroll
        for (int nt = 0; nt < 4; nt++) {
            int c = cb + wn * 32 + nt * 8 + qid * 2;
            *(float2*)&out[(size_t)row * D_ + c] =
                make_float2(acc[mt][nt][0], acc[mt][nt][1]);
            *(float2*)&out[(size_t)(row + 8) * D_ + c] =
                make_float2(acc[mt][nt][2], acc[mt][nt][3]);
        }
    }
}

// =========================================================================
extern "C" void kernel_launch(void* const* d_in, const int* in_sizes, int n_in,
                              void* d_out, int out_size)
{
    const float* tokens        = (const float*)d_in[0];
    const unsigned char* mask  = (const unsigned char*)d_in[1];
    const float* W1            = (const float*)d_in[2];
    const float* b1            = (const float*)d_in[3];
    const float* W2            = (const float*)d_in[4];
    const float* b2            = (const float*)d_in[5];
    float* out                 = (float*)d_out;

    const int massSmem = (4 * T_ + 3 * 256 * 8) * 4;   // 57344 bytes
    cudaFuncSetAttribute(mass_kernel,
                         cudaFuncAttributeMaxDynamicSharedMemorySize, massSmem);
    cudaFuncSetAttribute(mlp_mma,
                         cudaFuncAttributeMaxDynamicSharedMemorySize, 49152);

    setup_kernel<<<208, 256>>>(tokens, mask, W2);
    mass_kernel<<<dim3(T_ / 32, B_), 256, massSmem>>>(W1, b1);
    mlp_mma<<<(B_ * T_ / 128) * 8, 256, 49152>>>(b2, out);
}

// round 15
// speedup vs baseline: 1.0186x; 1.0186x over previous
#include <cuda_runtime.h>
#include <cuda_bf16.h>
#include <math.h>
#include <stdint.h>
#include <float.h>

#define B_ 16
#define T_ 2048
#define D_ 512
#define H_ 64

typedef unsigned long long u64;

// ---------------- device scratch (no allocations allowed) ----------------
__device__ float4 g_P[B_ * T_];                    // 4-momenta
__device__ int    g_len[B_];                       // valid lengths per batch
__device__ __nv_bfloat16 g_Ahi[B_ * T_ * H_];      // h split hi
__device__ __nv_bfloat16 g_Alo[B_ * T_ * H_];      // h split lo
__device__ __nv_bfloat16 g_Bhi[D_ * H_];           // W2^T split hi  [n][k]
__device__ __nv_bfloat16 g_Blo[D_ * H_];           // W2^T split lo  [n][k]

// ---------------- f32x2 packed helpers ----------------
__device__ __forceinline__ u64 dup2(float a) {
    u64 r; asm("mov.b64 %0, {%1, %1};" : "=l"(r) : "f"(a)); return r;
}
__device__ __forceinline__ float2 unpack2(u64 v) {
    float2 f; asm("mov.b64 {%0, %1}, %2;" : "=f"(f.x), "=f"(f.y) : "l"(v)); return f;
}
__device__ __forceinline__ u64 fma2(u64 a, u64 b, u64 c) {
    u64 d; asm("fma.rn.f32x2 %0, %1, %2, %3;" : "=l"(d) : "l"(a), "l"(b), "l"(c)); return d;
}
__device__ __forceinline__ u64 mul2(u64 a, u64 b) {
    u64 d; asm("mul.rn.f32x2 %0, %1, %2;" : "=l"(d) : "l"(a), "l"(b)); return d;
}
__device__ __forceinline__ float gelu(float x) {
    return 0.5f * x * (1.f + erff(x * 0.70710678118654752f));
}
__device__ __forceinline__ uint32_t smem_u32(const void* p) {
    uint32_t a;
    asm("{ .reg .u64 t; cvta.to.shared.u64 t, %1; cvt.u32.u64 %0, t; }"
        : "=r"(a) : "l"(p));
    return a;
}

// bf16 mma m16n8k16, f32 accum (plain PTX, sm_80+, OK on sm_103 target)
#define MMA16816(d, a, b) \
    asm volatile("mma.sync.aligned.m16n8k16.row.col.f32.bf16.bf16.f32 " \
        "{%0,%1,%2,%3}, {%4,%5,%6,%7}, {%8,%9}, {%0,%1,%2,%3};" \
        : "+f"((d)[0]), "+f"((d)[1]), "+f"((d)[2]), "+f"((d)[3]) \
        : "r"((a)[0]), "r"((a)[1]), "r"((a)[2]), "r"((a)[3]), \
          "r"((b)[0]), "r"((b)[1]))

__device__ __forceinline__ void ldm_x4(uint32_t* r, uint32_t saddr) {
    asm volatile("ldmatrix.sync.aligned.m8n8.x4.shared.b16 {%0,%1,%2,%3}, [%4];"
        : "=r"(r[0]), "=r"(r[1]), "=r"(r[2]), "=r"(r[3]) : "r"(saddr));
}

#define SWZ(o) ((o) ^ (((o) >> 3) & 0x70))

// =========================================================================
// Kernel 0: fused setup (prep / len / w2t by block range).
// =========================================================================
__global__ __launch_bounds__(256) void setup_kernel(
    const float* __restrict__ tokens, const unsigned char* __restrict__ mask,
    const float* __restrict__ W2)
{
    int bid = blockIdx.x;
    int tid = threadIdx.x;

    if (bid < 64) {
        int gt0 = bid * 512 + tid;
        int gt1 = gt0 + 256;
        float4 tk0 = ((const float4*)tokens)[gt0];
        float4 tk1 = ((const float4*)tokens)[gt1];
        float e0 = fminf(fmaxf(tk0.z, -20.f), 20.f);
        float e1 = fminf(fmaxf(tk1.z, -20.f), 20.f);
        float sp0, cp0, sp1, cp1;
        sincosf(tk0.w, &sp0, &cp0);
        sincosf(tk1.w, &sp1, &cp1);
        float sh0 = sinhf(e0);
        float sh1 = sinhf(e1);
        g_P[gt0] = make_float4(tk0.x, tk0.y * cp0, tk0.y * sp0, tk0.y * sh0);
        g_P[gt1] = make_float4(tk1.x, tk1.y * cp1, tk1.y * sp1, tk1.y * sh1);
    } else if (bid < 80) {
        int b = bid - 64;
        unsigned int w0 = *(const unsigned int*)mask;
        bool byteMode = (w0 == 0x01010101u);
        int cnt = 0;
        for (int s = tid; s < T_; s += 256) {
            unsigned int mv = byteMode ? (unsigned int)mask[b * T_ + s]
                                       : ((const unsigned int*)mask)[b * T_ + s];
            cnt += (mv != 0u);
        }
        for (int o = 16; o; o >>= 1) cnt += __shfl_down_sync(0xffffffffu, cnt, o);
        __shared__ int sred[8];
        if ((tid & 31) == 0) sred[tid >> 5] = cnt;
        __syncthreads();
        if (tid == 0) {
            int tot = 0;
#pragma unroll
            for (int i = 0; i < 8; i++) tot += sred[i];
            g_len[b] = tot;
        }
    } else {
        int idx = (bid - 80) * 256 + tid;
        int k = idx >> 9;
        int n = idx & 511;
        float wv = W2[k * D_ + n];
        __nv_bfloat16 h = __float2bfloat16(wv);
        g_Bhi[n * H_ + k] = h;
        g_Blo[n * H_ + k] = __float2bfloat16(wv - __bfloat162float(h));
    }
}

// =========================================================================
// Kernel 2: per-token top-8 Minkowski dot -> masses -> FUSED h (bf16 split).
// Block = 512 threads = 64 tokens: 16 warps = 2 token-groups x 8 eighths.
// Warp w: token group tg = w>>3 (32 tokens, lane<->token), eighth we = w&7.
// 2 blocks/SM (80 KB smem) -> 8 warps/SMSP.
// =========================================================================
#define CEA(a, b) do { float _l = fminf(a, b), _h = fmaxf(a, b); (a) = _l; (b) = _h; } while (0)

#define SORT8A(v0,v1,v2,v3,v4,v5,v6,v7) do {                 \
    CEA(v0, v1); CEA(v2, v3); CEA(v4, v5); CEA(v6, v7);      \
    CEA(v0, v2); CEA(v1, v3); CEA(v4, v6); CEA(v5, v7);      \
    CEA(v1, v2); CEA(v5, v6);                                \
    CEA(v0, v4); CEA(v1, v5); CEA(v2, v6); CEA(v3, v7);      \
    CEA(v2, v4); CEA(v3, v5);                                \
    CEA(v1, v2); CEA(v3, v4); CEA(v5, v6);                   \
} while (0)

#define CLEAN8(m0,m1,m2,m3,m4,m5,m6,m7) do {                 \
    CEA(m0, m4); CEA(m1, m5); CEA(m2, m6); CEA(m3, m7);      \
    CEA(m0, m2); CEA(m1, m3); CEA(m4, m6); CEA(m5, m7);      \
    CEA(m0, m1); CEA(m2, m3); CEA(m4, m5); CEA(m6, m7);      \
} while (0)

#define VINS(dv) do { float c = (dv), t_;                 \
    t_ = fminf(c, th1); c = fmaxf(c, th1); th0 = t_;      \
    t_ = fminf(c, th2); c = fmaxf(c, th2); th1 = t_;      \
    t_ = fminf(c, th3); c = fmaxf(c, th3); th2 = t_;      \
    t_ = fminf(c, th4); c = fmaxf(c, th4); th3 = t_;      \
    t_ = fminf(c, th5); c = fmaxf(c, th5); th4 = t_;      \
    t_ = fminf(c, th6); c = fmaxf(c, th6); th5 = t_;      \
    t_ = fminf(c, th7); c = fmaxf(c, th7); th6 = t_;      \
    th7 = c;                                              \
} while (0)

#define CAPTURE(dv, si) do {                                          \
    float _d = (dv);                                                  \
    if (_d >= th) {                                                   \
        if (_d > th) {                                                \
            if (na < 8) { av[na] = _d; ai[na] = (si); na++; }         \
        } else {                                                      \
            if (nb < 8) { bi[nb] = (si); nb++; }                      \
        }                                                             \
    }                                                                 \
} while (0)

__device__ __forceinline__ void dot8f(
    const float* sE, const float* sX, const float* sY, const float* sZ,
    int s, u64 aE2, u64 ax2, u64 ay2, u64 az2, float* v)
{
    ulonglong2 E01 = *(const ulonglong2*)&sE[s];
    ulonglong2 X01 = *(const ulonglong2*)&sX[s];
    ulonglong2 Y01 = *(const ulonglong2*)&sY[s];
    ulonglong2 Z01 = *(const ulonglong2*)&sZ[s];
    u64 p0 = fma2(aE2, E01.x, fma2(ax2, X01.x, fma2(ay2, Y01.x, mul2(az2, Z01.x))));
    u64 p1 = fma2(aE2, E01.y, fma2(ax2, X01.y, fma2(ay2, Y01.y, mul2(az2, Z01.y))));
    float2 d0 = unpack2(p0), d1 = unpack2(p1);
    v[0] = d0.x; v[1] = d0.y; v[2] = d1.x; v[3] = d1.y;
}

// per-thread h-chunk: token gt (global), hidden [hh, hh+8)
__device__ __forceinline__ void emit_h_chunk(
    int gt, int hh, float m0, float m1, float m2,
    const float* sW1s, const float* sb1s)
{
    __align__(16) __nv_bfloat16 hi8[8];
    __align__(16) __nv_bfloat16 lo8[8];
#pragma unroll
    for (int j = 0; j < 8; j++) {
        int k = hh + j;
        float x = fmaf(m0, sW1s[k], fmaf(m1, sW1s[H_ + k],
                  fmaf(m2, sW1s[2 * H_ + k], sb1s[k])));
        float g = gelu(x);
        __nv_bfloat16 h = __float2bfloat16(g);
        hi8[j] = h;
        lo8[j] = __float2bfloat16(g - __bfloat162float(h));
    }
    *(uint4*)&g_Ahi[(size_t)gt * H_ + hh] = *(const uint4*)hi8;
    *(uint4*)&g_Alo[(size_t)gt * H_ + hh] = *(const uint4*)lo8;
}

__global__ __launch_bounds__(512) void mass_kernel(
    const float* __restrict__ W1, const float* __restrict__ b1)
{
    extern __shared__ __align__(16) unsigned char smem_raw[];
    float* sE  = (float*)smem_raw;
    float* sX  = sE + T_;
    float* sY  = sX + T_;
    float* sZ  = sY + T_;
    float* sAv = sZ + T_;                     // [512*8]
    int*   sAi = (int*)(sAv + 512 * 8);       // [512*8]
    int*   sBi = sAi + 512 * 8;               // [512*8]
    __shared__ float sM[64 * 3];
    __shared__ float sW1s[3 * H_];
    __shared__ float sb1s[H_];

    int b = blockIdx.y;
    int len = g_len[b];
    int tbase0 = blockIdx.x * 64;
    int tid = threadIdx.x, lane = tid & 31, w = tid >> 5;
    int tg = w >> 3, we = w & 7;
    float mv = sqrtf(1e-8f);

    if (tid < 3 * H_) sW1s[tid] = W1[tid];
    if (tid < H_) sb1s[tid] = b1[tid];

    if (tbase0 >= len) {                 // whole 64-token block masked
        __syncthreads();
        int tt = tid >> 3;               // 0..63
        int hh = (tid & 7) * 8;
        emit_h_chunk(b * T_ + tbase0 + tt, hh, mv, mv, mv, sW1s, sb1s);
        return;
    }

    const float4* gp = g_P + b * T_;
    for (int i = tid; i < T_; i += 512) {
        float4 p = gp[i];
        sE[i] = p.x; sX[i] = p.y; sY[i] = p.z; sZ[i] = p.w;
    }
    __syncthreads();

    int t = tbase0 + tg * 32 + lane;
    int q0 = (we * len) >> 3;
    int q1 = ((we + 1) * len) >> 3;

    float aE = sE[t], ax = -sX[t], ay = -sY[t], az = -sZ[t];
    u64 aE2 = dup2(aE), ax2 = dup2(ax), ay2 = dup2(ay), az2 = dup2(az);

    float th0 = -FLT_MAX, th1 = -FLT_MAX, th2 = -FLT_MAX, th3 = -FLT_MAX;
    float th4 = -FLT_MAX, th5 = -FLT_MAX, th6 = -FLT_MAX, th7 = -FLT_MAX;

    int s0 = (q0 + 3) & ~3; if (s0 > q1) s0 = q1;
    int s1a = s0 + ((q1 - s0) & ~15);

    // ---- pass 1: always-sort batched top-8 (value-multiset exact) ----
    for (int s = q0; s < s0; s++) {
        float d = fmaf(aE, sE[s], fmaf(ax, sX[s], fmaf(ay, sY[s], az * sZ[s])));
        if (d > th0) VINS(d);
    }
    for (int s = s0; s < s1a; s += 16) {
        float v[16];
        dot8f(sE, sX, sY, sZ, s,      aE2, ax2, ay2, az2, v);
        dot8f(sE, sX, sY, sZ, s + 4,  aE2, ax2, ay2, az2, v + 4);
        dot8f(sE, sX, sY, sZ, s + 8,  aE2, ax2, ay2, az2, v + 8);
        dot8f(sE, sX, sY, sZ, s + 12, aE2, ax2, ay2, az2, v + 12);
        SORT8A(v[0], v[1], v[2], v[3], v[4], v[5], v[6], v[7]);
        SORT8A(v[8], v[9], v[10], v[11], v[12], v[13], v[14], v[15]);
        float m0 = fmaxf(v[0], v[15]), m1 = fmaxf(v[1], v[14]);
        float m2 = fmaxf(v[2], v[13]), m3 = fmaxf(v[3], v[12]);
        float m4 = fmaxf(v[4], v[11]), m5 = fmaxf(v[5], v[10]);
        float m6 = fmaxf(v[6], v[9]),  m7 = fmaxf(v[7], v[8]);
        CLEAN8(m0, m1, m2, m3, m4, m5, m6, m7);
        float u0 = fmaxf(th0, m7), u1 = fmaxf(th1, m6);
        float u2 = fmaxf(th2, m5), u3 = fmaxf(th3, m4);
        float u4 = fmaxf(th4, m3), u5 = fmaxf(th5, m2);
        float u6 = fmaxf(th6, m1), u7 = fmaxf(th7, m0);
        CLEAN8(u0, u1, u2, u3, u4, u5, u6, u7);
        th0 = u0; th1 = u1; th2 = u2; th3 = u3;
        th4 = u4; th5 = u5; th6 = u6; th7 = u7;
    }
    for (int s = s1a; s < q1; s++) {
        float d = fmaf(aE, sE[s], fmaf(ax, sX[s], fmaf(ay, sY[s], az * sZ[s])));
        if (d > th0) VINS(d);
    }

    // ---- pass 2: tie-exact index capture in ascending s ----
    float th = th0;
    float* av = &sAv[tid * 8];
    int*   ai = &sAi[tid * 8];
    int*   bi = &sBi[tid * 8];
    int na = 0, nb = 0;

    for (int s = q0; s < s0; s++) {
        float d = fmaf(aE, sE[s], fmaf(ax, sX[s], fmaf(ay, sY[s], az * sZ[s])));
        CAPTURE(d, s);
    }
    for (int s = s0; s < s1a; s += 16) {
        float v[16];
        dot8f(sE, sX, sY, sZ, s,      aE2, ax2, ay2, az2, v);
        dot8f(sE, sX, sY, sZ, s + 4,  aE2, ax2, ay2, az2, v + 4);
        dot8f(sE, sX, sY, sZ, s + 8,  aE2, ax2, ay2, az2, v + 8);
        dot8f(sE, sX, sY, sZ, s + 12, aE2, ax2, ay2, az2, v + 12);
        float g0 = fmaxf(fmaxf(v[0], v[1]), fmaxf(v[2], v[3]));
        float g1 = fmaxf(fmaxf(v[4], v[5]), fmaxf(v[6], v[7]));
        float g2 = fmaxf(fmaxf(v[8], v[9]), fmaxf(v[10], v[11]));
        float g3 = fmaxf(fmaxf(v[12], v[13]), fmaxf(v[14], v[15]));
        if (fmaxf(fmaxf(g0, g1), fmaxf(g2, g3)) >= th) {
#pragma unroll
            for (int k = 0; k < 16; k++) CAPTURE(v[k], s + k);
        }
    }
    for (int s = s1a; s < q1; s++) {
        float d = fmaf(aE, sE[s], fmaf(ax, sX[s], fmaf(ay, sY[s], az * sZ[s])));
        CAPTURE(d, s);
    }

    // ---- build eighth list: stable-desc-sort(A) ++ ties(B asc index) ----
    {
        float v[8]; int idA[8]; int bReg[8];
#pragma unroll
        for (int j = 0; j < 8; j++) {
            v[j]   = (j < na) ? av[j] : -FLT_MAX;
            idA[j] = (j < na) ? ai[j] : 0;
            bReg[j] = bi[j];
        }
#pragma unroll
        for (int i = 0; i < 7; i++) {
#pragma unroll
            for (int j = 0; j < 7 - i; j++) {
                bool p = v[j + 1] > v[j];
                float hv = p ? v[j + 1] : v[j];
                float lv = p ? v[j] : v[j + 1];
                int hi_ = p ? idA[j + 1] : idA[j];
                int lo_ = p ? idA[j] : idA[j + 1];
                v[j] = hv; v[j + 1] = lv; idA[j] = hi_; idA[j + 1] = lo_;
            }
        }
#pragma unroll
        for (int j = 0; j < 8; j++) {
            int jb = j - na; jb = jb < 0 ? 0 : (jb > 7 ? 7 : jb);
            av[j] = (j < na) ? v[j] : th;
            ai[j] = (j < na) ? idA[j] : bReg[jb];
        }
    }
    __syncthreads();

    // ---- warps 0 and 8: 8-way merge + cumsum for their token group ----
    if (we == 0) {
        int goff = tg * 256;                // tid base of this group's lists
        int tt = tbase0 + tg * 32 + lane;
        if (tt >= len) {
            sM[(tg * 32 + lane) * 3 + 0] = mv;
            sM[(tg * 32 + lane) * 3 + 1] = mv;
            sM[(tg * 32 + lane) * 3 + 2] = mv;
        } else {
            float vh[8]; int pp[8];
#pragma unroll
            for (int q = 0; q < 8; q++) {
                pp[q] = 0;
                vh[q] = sAv[(goff + q * 32 + lane) * 8];
            }
            float cE = 0.f, cX = 0.f, cY = 0.f, cZ = 0.f;
            float m[3]; int kk = 0;
#pragma unroll
            for (int j = 0; j < 8; j++) {
                int bq = 0; float bv = vh[0];
#pragma unroll
                for (int q = 1; q < 8; q++)
                    if (vh[q] > bv) { bv = vh[q]; bq = q; }   // tie -> lower eighth
                int ix = 0;
#pragma unroll
                for (int q = 0; q < 8; q++) {
                    if (bq == q) {
                        ix = sAi[(goff + q * 32 + lane) * 8 + pp[q]];
                        pp[q]++;
                        vh[q] = (pp[q] < 8) ? sAv[(goff + q * 32 + lane) * 8 + pp[q]] : -FLT_MAX;
                    }
                }
                cE += sE[ix]; cX += sX[ix]; cY += sY[ix]; cZ += sZ[ix];
                if (j == 1 || j == 3 || j == 7) {
                    float m2 = fmaf(cE, cE, -fmaf(cX, cX, fmaf(cY, cY, cZ * cZ)));
                    m[kk++] = sqrtf(fmaxf(m2, 0.f) + 1e-8f);
                }
            }
            sM[(tg * 32 + lane) * 3 + 0] = m[0];
            sM[(tg * 32 + lane) * 3 + 1] = m[1];
            sM[(tg * 32 + lane) * 3 + 2] = m[2];
        }
    }
    __syncthreads();

    // ---- fused h: 512 threads = 64 tokens x 8 hidden-chunks ----
    {
        int tt = tid >> 3;                 // 0..63
        int hh = (tid & 7) * 8;
        float m0 = sM[tt * 3 + 0];
        float m1 = sM[tt * 3 + 1];
        float m2 = sM[tt * 3 + 2];
        emit_h_chunk(b * T_ + tbase0 + tt, hh, m0, m1, m2, sW1s, sb1s);
    }
}

// =========================================================================
// Kernel 3: out = h @ W2 + b2 via mma.sync (split bf16, 3 terms).
// Block = 256 thr (8 warps): 128 tokens x 64 cols; warp = 32 tok x 32 col.
// =========================================================================
__global__ __launch_bounds__(256) void mlp_mma(
    const float* __restrict__ b2, float* __restrict__ out)
{
    extern __shared__ __align__(1024) unsigned char sm[];
    unsigned char* sAhi = sm;                  // 16K
    unsigned char* sAlo = sm + 16384;          // 16K
    unsigned char* sBhi = sm + 32768;          // 8K
    unsigned char* sBlo = sm + 40960;          // 8K  (total 48K)

    int tid = threadIdx.x, lane = tid & 31, w = tid >> 5;
    int cb = (blockIdx.x & 7) * 64;
    int tok0 = (blockIdx.x >> 3) * 128;
    int wm = w & 3, wn = w >> 2;
    int qid = lane & 3, grp = lane >> 2;
    int rl = lane & 15, cl = lane >> 4;

#pragma unroll
    for (int i = 0; i < 4; i++) {
        int idx = i * 256 + tid;
        int row = idx >> 3, c = idx & 7;
        uint32_t o = SWZ((uint32_t)(row * 128 + c * 16));
        *(uint4*)(sAhi + o) = ((const uint4*)(g_Ahi + (size_t)(tok0 + row) * H_))[c];
        *(uint4*)(sAlo + o) = ((const uint4*)(g_Alo + (size_t)(tok0 + row) * H_))[c];
    }
#pragma unroll
    for (int i = 0; i < 2; i++) {
        int idx = i * 256 + tid;
        int row = idx >> 3, c = idx & 7;
        uint32_t o = SWZ((uint32_t)(row * 128 + c * 16));
        *(uint4*)(sBhi + o) = ((const uint4*)(g_Bhi + (size_t)(cb + row) * H_))[c];
        *(uint4*)(sBlo + o) = ((const uint4*)(g_Blo + (size_t)(cb + row) * H_))[c];
    }
    __syncthreads();

    uint32_t aAhi = smem_u32(sAhi), aAlo = smem_u32(sAlo);
    uint32_t aBhi = smem_u32(sBhi), aBlo = smem_u32(sBlo);

    float acc[2][4][4];
#pragma unroll
    for (int nt = 0; nt < 4; nt++) {
        float2 bv = *(const float2*)&b2[cb + wn * 32 + nt * 8 + qid * 2];
#pragma unroll
        for (int mt = 0; mt < 2; mt++) {
            acc[mt][nt][0] = bv.x; acc[mt][nt][1] = bv.y;
            acc[mt][nt][2] = bv.x; acc[mt][nt][3] = bv.y;
        }
    }

#pragma unroll
    for (int ks = 0; ks < 4; ks++) {
        uint32_t ah[2][4], al[2][4];
#pragma unroll
        for (int mt = 0; mt < 2; mt++) {
            uint32_t o = SWZ((uint32_t)((wm * 32 + mt * 16 + rl) * 128 + (ks * 2 + cl) * 16));
            ldm_x4(ah[mt], aAhi + o);
            ldm_x4(al[mt], aAlo + o);
        }
#pragma unroll
        for (int ntp = 0; ntp < 2; ntp++) {
            uint32_t bh[4], bl[4];
            uint32_t ob = SWZ((uint32_t)((wn * 32 + ntp * 16 + rl) * 128 + (ks * 2 + cl) * 16));
            ldm_x4(bh, aBhi + ob);
            ldm_x4(bl, aBlo + ob);
            uint32_t bfh0[2] = {bh[0], bh[2]}, bfh1[2] = {bh[1], bh[3]};
            uint32_t bfl0[2] = {bl[0], bl[2]}, bfl1[2] = {bl[1], bl[3]};
#pragma unroll
            for (int mt = 0; mt < 2; mt++) {
                MMA16816(acc[mt][ntp * 2],     ah[mt], bfh0);
                MMA16816(acc[mt][ntp * 2],     ah[mt], bfl0);
                MMA16816(acc[mt][ntp * 2],     al[mt], bfh0);
                MMA16816(acc[mt][ntp * 2 + 1], ah[mt], bfh1);
                MMA16816(acc[mt][ntp * 2 + 1], ah[mt], bfl1);
                MMA16816(acc[mt][ntp * 2 + 1], al[mt], bfh1);
            }
        }
    }

#pragma unroll
    for (int mt = 0; mt < 2; mt++) {
        int row = tok0 + wm * 32 + mt * 16 + grp;
#pragma unroll
        for (int nt = 0; nt < 4; nt++) {
            int c = cb + wn * 32 + nt * 8 + qid * 2;
            *(float2*)&out[(size_t)row * D_ + c] =
                make_float2(acc[mt][nt][0], acc[mt][nt][1]);
            *(float2*)&out[(size_t)(row + 8) * D_ + c] =
                make_float2(acc[mt][nt][2], acc[mt][nt][3]);
        }
    }
}

// =========================================================================
extern "C" void kernel_launch(void* const* d_in, const int* in_sizes, int n_in,
                              void* d_out, int out_size)
{
    const float* tokens        = (const float*)d_in[0];
    const unsigned char* mask  = (const unsigned char*)d_in[1];
    const float* W1            = (const float*)d_in[2];
    const float* b1            = (const float*)d_in[3];
    const float* W2            = (const float*)d_in[4];
    const float* b2            = (const float*)d_in[5];
    float* out                 = (float*)d_out;

    const int massSmem = (4 * T_ + 3 * 512 * 8) * 4;   // 81920 bytes
    cudaFuncSetAttribute(mass_kernel,
                         cudaFuncAttributeMaxDynamicSharedMemorySize, massSmem);
    cudaFuncSetAttribute(mlp_mma,
                         cudaFuncAttributeMaxDynamicSharedMemorySize, 49152);

    setup_kernel<<<208, 256>>>(tokens, mask, W2);
    mass_kernel<<<dim3(T_ / 64, B_), 512, massSmem>>>(W1, b1);
    mlp_mma<<<(B_ * T_ / 128) * 8, 256, 49152>>>(b2, out);
}

// round 16
// speedup vs baseline: 1.0830x; 1.0632x over previous
#include <cuda_runtime.h>
#include <cuda_fp16.h>
#include <math.h>
#include <stdint.h>
#include <float.h>

#define B_ 16
#define T_ 2048
#define D_ 512
#define H_ 64

typedef unsigned long long u64;

// ---------------- device scratch (no allocations allowed) ----------------
__device__ float4 g_P[B_ * T_];                    // 4-momenta
__device__ int    g_len[B_];                       // valid lengths per batch
__device__ __half g_Ahi[B_ * T_ * H_];             // h split hi (fp16)
__device__ __half g_Alo[B_ * T_ * H_];             // h split lo (fp16)
__device__ __half g_Bh[D_ * H_];                   // W2^T fp16  [n][k]

// ---------------- f32x2 packed helpers ----------------
__device__ __forceinline__ u64 dup2(float a) {
    u64 r; asm("mov.b64 %0, {%1, %1};" : "=l"(r) : "f"(a)); return r;
}
__device__ __forceinline__ float2 unpack2(u64 v) {
    float2 f; asm("mov.b64 {%0, %1}, %2;" : "=f"(f.x), "=f"(f.y) : "l"(v)); return f;
}
__device__ __forceinline__ u64 fma2(u64 a, u64 b, u64 c) {
    u64 d; asm("fma.rn.f32x2 %0, %1, %2, %3;" : "=l"(d) : "l"(a), "l"(b), "l"(c)); return d;
}
__device__ __forceinline__ u64 mul2(u64 a, u64 b) {
    u64 d; asm("mul.rn.f32x2 %0, %1, %2;" : "=l"(d) : "l"(a), "l"(b)); return d;
}
__device__ __forceinline__ float gelu(float x) {
    return 0.5f * x * (1.f + erff(x * 0.70710678118654752f));
}
__device__ __forceinline__ uint32_t smem_u32(const void* p) {
    uint32_t a;
    asm("{ .reg .u64 t; cvta.to.shared.u64 t, %1; cvt.u32.u64 %0, t; }"
        : "=r"(a) : "l"(p));
    return a;
}

// fp16 mma m16n8k16, f32 accum
#define MMA16816F(d, a, b) \
    asm volatile("mma.sync.aligned.m16n8k16.row.col.f32.f16.f16.f32 " \
        "{%0,%1,%2,%3}, {%4,%5,%6,%7}, {%8,%9}, {%0,%1,%2,%3};" \
        : "+f"((d)[0]), "+f"((d)[1]), "+f"((d)[2]), "+f"((d)[3]) \
        : "r"((a)[0]), "r"((a)[1]), "r"((a)[2]), "r"((a)[3]), \
          "r"((b)[0]), "r"((b)[1]))

__device__ __forceinline__ void ldm_x4(uint32_t* r, uint32_t saddr) {
    asm volatile("ldmatrix.sync.aligned.m8n8.x4.shared.b16 {%0,%1,%2,%3}, [%4];"
        : "=r"(r[0]), "=r"(r[1]), "=r"(r[2]), "=r"(r[3]) : "r"(saddr));
}

#define SWZ(o) ((o) ^ (((o) >> 3) & 0x70))

// =========================================================================
// Kernel 0: fused setup (prep / len / w2t by block range).
// =========================================================================
__global__ __launch_bounds__(256) void setup_kernel(
    const float* __restrict__ tokens, const unsigned char* __restrict__ mask,
    const float* __restrict__ W2)
{
    int bid = blockIdx.x;
    int tid = threadIdx.x;

    if (bid < 64) {
        int gt0 = bid * 512 + tid;
        int gt1 = gt0 + 256;
        float4 tk0 = ((const float4*)tokens)[gt0];
        float4 tk1 = ((const float4*)tokens)[gt1];
        float e0 = fminf(fmaxf(tk0.z, -20.f), 20.f);
        float e1 = fminf(fmaxf(tk1.z, -20.f), 20.f);
        float sp0, cp0, sp1, cp1;
        sincosf(tk0.w, &sp0, &cp0);
        sincosf(tk1.w, &sp1, &cp1);
        float sh0 = sinhf(e0);
        float sh1 = sinhf(e1);
        g_P[gt0] = make_float4(tk0.x, tk0.y * cp0, tk0.y * sp0, tk0.y * sh0);
        g_P[gt1] = make_float4(tk1.x, tk1.y * cp1, tk1.y * sp1, tk1.y * sh1);
    } else if (bid < 80) {
        int b = bid - 64;
        unsigned int w0 = *(const unsigned int*)mask;
        bool byteMode = (w0 == 0x01010101u);
        int cnt = 0;
        for (int s = tid; s < T_; s += 256) {
            unsigned int mv = byteMode ? (unsigned int)mask[b * T_ + s]
                                       : ((const unsigned int*)mask)[b * T_ + s];
            cnt += (mv != 0u);
        }
        for (int o = 16; o; o >>= 1) cnt += __shfl_down_sync(0xffffffffu, cnt, o);
        __shared__ int sred[8];
        if ((tid & 31) == 0) sred[tid >> 5] = cnt;
        __syncthreads();
        if (tid == 0) {
            int tot = 0;
#pragma unroll
            for (int i = 0; i < 8; i++) tot += sred[i];
            g_len[b] = tot;
        }
    } else {
        int idx = (bid - 80) * 256 + tid;
        int k = idx >> 9;
        int n = idx & 511;
        g_Bh[n * H_ + k] = __float2half(W2[k * D_ + n]);
    }
}

// =========================================================================
// Kernel 2: per-token top-8 Minkowski dot -> masses -> FUSED h (fp16 split).
// Block = 512 threads = 64 tokens: 16 warps = 2 token-groups x 8 eighths.
// =========================================================================
#define CEA(a, b) do { float _l = fminf(a, b), _h = fmaxf(a, b); (a) = _l; (b) = _h; } while (0)

#define SORT8A(v0,v1,v2,v3,v4,v5,v6,v7) do {                 \
    CEA(v0, v1); CEA(v2, v3); CEA(v4, v5); CEA(v6, v7);      \
    CEA(v0, v2); CEA(v1, v3); CEA(v4, v6); CEA(v5, v7);      \
    CEA(v1, v2); CEA(v5, v6);                                \
    CEA(v0, v4); CEA(v1, v5); CEA(v2, v6); CEA(v3, v7);      \
    CEA(v2, v4); CEA(v3, v5);                                \
    CEA(v1, v2); CEA(v3, v4); CEA(v5, v6);                   \
} while (0)

#define CLEAN8(m0,m1,m2,m3,m4,m5,m6,m7) do {                 \
    CEA(m0, m4); CEA(m1, m5); CEA(m2, m6); CEA(m3, m7);      \
    CEA(m0, m2); CEA(m1, m3); CEA(m4, m6); CEA(m5, m7);      \
    CEA(m0, m1); CEA(m2, m3); CEA(m4, m5); CEA(m6, m7);      \
} while (0)

#define VINS(dv) do { float c = (dv), t_;                 \
    t_ = fminf(c, th1); c = fmaxf(c, th1); th0 = t_;      \
    t_ = fminf(c, th2); c = fmaxf(c, th2); th1 = t_;      \
    t_ = fminf(c, th3); c = fmaxf(c, th3); th2 = t_;      \
    t_ = fminf(c, th4); c = fmaxf(c, th4); th3 = t_;      \
    t_ = fminf(c, th5); c = fmaxf(c, th5); th4 = t_;      \
    t_ = fminf(c, th6); c = fmaxf(c, th6); th5 = t_;      \
    t_ = fminf(c, th7); c = fmaxf(c, th7); th6 = t_;      \
    th7 = c;                                              \
} while (0)

#define CAPTURE(dv, si) do {                                          \
    float _d = (dv);                                                  \
    if (_d >= th) {                                                   \
        if (_d > th) {                                                \
            if (na < 8) { av[na] = _d; ai[na] = (si); na++; }         \
        } else {                                                      \
            if (nb < 8) { bi[nb] = (si); nb++; }                      \
        }                                                             \
    }                                                                 \
} while (0)

__device__ __forceinline__ void dot8f(
    const float* sE, const float* sX, const float* sY, const float* sZ,
    int s, u64 aE2, u64 ax2, u64 ay2, u64 az2, float* v)
{
    ulonglong2 E01 = *(const ulonglong2*)&sE[s];
    ulonglong2 X01 = *(const ulonglong2*)&sX[s];
    ulonglong2 Y01 = *(const ulonglong2*)&sY[s];
    ulonglong2 Z01 = *(const ulonglong2*)&sZ[s];
    u64 p0 = fma2(aE2, E01.x, fma2(ax2, X01.x, fma2(ay2, Y01.x, mul2(az2, Z01.x))));
    u64 p1 = fma2(aE2, E01.y, fma2(ax2, X01.y, fma2(ay2, Y01.y, mul2(az2, Z01.y))));
    float2 d0 = unpack2(p0), d1 = unpack2(p1);
    v[0] = d0.x; v[1] = d0.y; v[2] = d1.x; v[3] = d1.y;
}

// per-thread h-chunk: token gt (global), hidden [hh, hh+8) -> fp16 hi/lo
__device__ __forceinline__ void emit_h_chunk(
    int gt, int hh, float m0, float m1, float m2,
    const float* sW1s, const float* sb1s)
{
    __align__(16) __half hi8[8];
    __align__(16) __half lo8[8];
#pragma unroll
    for (int j = 0; j < 8; j++) {
        int k = hh + j;
        float x = fmaf(m0, sW1s[k], fmaf(m1, sW1s[H_ + k],
                  fmaf(m2, sW1s[2 * H_ + k], sb1s[k])));
        float g = gelu(x);
        __half h = __float2half(g);
        hi8[j] = h;
        lo8[j] = __float2half(g - __half2float(h));
    }
    *(uint4*)&g_Ahi[(size_t)gt * H_ + hh] = *(const uint4*)hi8;
    *(uint4*)&g_Alo[(size_t)gt * H_ + hh] = *(const uint4*)lo8;
}

__global__ __launch_bounds__(512) void mass_kernel(
    const float* __restrict__ W1, const float* __restrict__ b1)
{
    extern __shared__ __align__(16) unsigned char smem_raw[];
    float* sE  = (float*)smem_raw;
    float* sX  = sE + T_;
    float* sY  = sX + T_;
    float* sZ  = sY + T_;
    float* sAv = sZ + T_;                     // [512*8]
    int*   sAi = (int*)(sAv + 512 * 8);       // [512*8]
    int*   sBi = sAi + 512 * 8;               // [512*8]
    __shared__ float sM[64 * 3];
    __shared__ float sW1s[3 * H_];
    __shared__ float sb1s[H_];

    int b = blockIdx.y;
    int len = g_len[b];
    int tbase0 = blockIdx.x * 64;
    int tid = threadIdx.x, lane = tid & 31, w = tid >> 5;
    int tg = w >> 3, we = w & 7;
    float mv = sqrtf(1e-8f);

    if (tid < 3 * H_) sW1s[tid] = W1[tid];
    if (tid < H_) sb1s[tid] = b1[tid];

    if (tbase0 >= len) {                 // whole 64-token block masked
        __syncthreads();
        int tt = tid >> 3;
        int hh = (tid & 7) * 8;
        emit_h_chunk(b * T_ + tbase0 + tt, hh, mv, mv, mv, sW1s, sb1s);
        return;
    }

    const float4* gp = g_P + b * T_;
    for (int i = tid; i < T_; i += 512) {
        float4 p = gp[i];
        sE[i] = p.x; sX[i] = p.y; sY[i] = p.z; sZ[i] = p.w;
    }
    __syncthreads();

    int t = tbase0 + tg * 32 + lane;
    int q0 = (we * len) >> 3;
    int q1 = ((we + 1) * len) >> 3;

    float aE = sE[t], ax = -sX[t], ay = -sY[t], az = -sZ[t];
    u64 aE2 = dup2(aE), ax2 = dup2(ax), ay2 = dup2(ay), az2 = dup2(az);

    float th0 = -FLT_MAX, th1 = -FLT_MAX, th2 = -FLT_MAX, th3 = -FLT_MAX;
    float th4 = -FLT_MAX, th5 = -FLT_MAX, th6 = -FLT_MAX, th7 = -FLT_MAX;

    int s0 = (q0 + 3) & ~3; if (s0 > q1) s0 = q1;
    int s1a = s0 + ((q1 - s0) & ~15);

    // ---- pass 1: always-sort batched top-8 (value-multiset exact) ----
    for (int s = q0; s < s0; s++) {
        float d = fmaf(aE, sE[s], fmaf(ax, sX[s], fmaf(ay, sY[s], az * sZ[s])));
        if (d > th0) VINS(d);
    }
    for (int s = s0; s < s1a; s += 16) {
        float v[16];
        dot8f(sE, sX, sY, sZ, s,      aE2, ax2, ay2, az2, v);
        dot8f(sE, sX, sY, sZ, s + 4,  aE2, ax2, ay2, az2, v + 4);
        dot8f(sE, sX, sY, sZ, s + 8,  aE2, ax2, ay2, az2, v + 8);
        dot8f(sE, sX, sY, sZ, s + 12, aE2, ax2, ay2, az2, v + 12);
        SORT8A(v[0], v[1], v[2], v[3], v[4], v[5], v[6], v[7]);
        SORT8A(v[8], v[9], v[10], v[11], v[12], v[13], v[14], v[15]);
        float m0 = fmaxf(v[0], v[15]), m1 = fmaxf(v[1], v[14]);
        float m2 = fmaxf(v[2], v[13]), m3 = fmaxf(v[3], v[12]);
        float m4 = fmaxf(v[4], v[11]), m5 = fmaxf(v[5], v[10]);
        float m6 = fmaxf(v[6], v[9]),  m7 = fmaxf(v[7], v[8]);
        CLEAN8(m0, m1, m2, m3, m4, m5, m6, m7);
        float u0 = fmaxf(th0, m7), u1 = fmaxf(th1, m6);
        float u2 = fmaxf(th2, m5), u3 = fmaxf(th3, m4);
        float u4 = fmaxf(th4, m3), u5 = fmaxf(th5, m2);
        float u6 = fmaxf(th6, m1), u7 = fmaxf(th7, m0);
        CLEAN8(u0, u1, u2, u3, u4, u5, u6, u7);
        th0 = u0; th1 = u1; th2 = u2; th3 = u3;
        th4 = u4; th5 = u5; th6 = u6; th7 = u7;
    }
    for (int s = s1a; s < q1; s++) {
        float d = fmaf(aE, sE[s], fmaf(ax, sX[s], fmaf(ay, sY[s], az * sZ[s])));
        if (d > th0) VINS(d);
    }

    // ---- pass 2: tie-exact index capture in ascending s ----
    float th = th0;
    float* av = &sAv[tid * 8];
    int*   ai = &sAi[tid * 8];
    int*   bi = &sBi[tid * 8];
    int na = 0, nb = 0;

    for (int s = q0; s < s0; s++) {
        float d = fmaf(aE, sE[s], fmaf(ax, sX[s], fmaf(ay, sY[s], az * sZ[s])));
        CAPTURE(d, s);
    }
    for (int s = s0; s < s1a; s += 16) {
        float v[16];
        dot8f(sE, sX, sY, sZ, s,      aE2, ax2, ay2, az2, v);
        dot8f(sE, sX, sY, sZ, s + 4,  aE2, ax2, ay2, az2, v + 4);
        dot8f(sE, sX, sY, sZ, s + 8,  aE2, ax2, ay2, az2, v + 8);
        dot8f(sE, sX, sY, sZ, s + 12, aE2, ax2, ay2, az2, v + 12);
        float g0 = fmaxf(fmaxf(v[0], v[1]), fmaxf(v[2], v[3]));
        float g1 = fmaxf(fmaxf(v[4], v[5]), fmaxf(v[6], v[7]));
        float g2 = fmaxf(fmaxf(v[8], v[9]), fmaxf(v[10], v[11]));
        float g3 = fmaxf(fmaxf(v[12], v[13]), fmaxf(v[14], v[15]));
        if (fmaxf(fmaxf(g0, g1), fmaxf(g2, g3)) >= th) {
#pragma unroll
            for (int k = 0; k < 16; k++) CAPTURE(v[k], s + k);
        }
    }
    for (int s = s1a; s < q1; s++) {
        float d = fmaf(aE, sE[s], fmaf(ax, sX[s], fmaf(ay, sY[s], az * sZ[s])));
        CAPTURE(d, s);
    }

    // ---- build eighth list: stable-desc-sort(A) ++ ties(B asc index) ----
    {
        float v[8]; int idA[8]; int bReg[8];
#pragma unroll
        for (int j = 0; j < 8; j++) {
            v[j]   = (j < na) ? av[j] : -FLT_MAX;
            idA[j] = (j < na) ? ai[j] : 0;
            bReg[j] = bi[j];
        }
#pragma unroll
        for (int i = 0; i < 7; i++) {
#pragma unroll
            for (int j = 0; j < 7 - i; j++) {
                bool p = v[j + 1] > v[j];
                float hv = p ? v[j + 1] : v[j];
                float lv = p ? v[j] : v[j + 1];
                int hi_ = p ? idA[j + 1] : idA[j];
                int lo_ = p ? idA[j] : idA[j + 1];
                v[j] = hv; v[j + 1] = lv; idA[j] = hi_; idA[j + 1] = lo_;
            }
        }
#pragma unroll
        for (int j = 0; j < 8; j++) {
            int jb = j - na; jb = jb < 0 ? 0 : (jb > 7 ? 7 : jb);
            av[j] = (j < na) ? v[j] : th;
            ai[j] = (j < na) ? idA[j] : bReg[jb];
        }
    }
    __syncthreads();

    // ---- warps 0 and 8: 8-way merge + cumsum for their token group ----
    if (we == 0) {
        int goff = tg * 256;
        int tt = tbase0 + tg * 32 + lane;
        if (tt >= len) {
            sM[(tg * 32 + lane) * 3 + 0] = mv;
            sM[(tg * 32 + lane) * 3 + 1] = mv;
            sM[(tg * 32 + lane) * 3 + 2] = mv;
        } else {
            float vh[8]; int pp[8];
#pragma unroll
            for (int q = 0; q < 8; q++) {
                pp[q] = 0;
                vh[q] = sAv[(goff + q * 32 + lane) * 8];
            }
            float cE = 0.f, cX = 0.f, cY = 0.f, cZ = 0.f;
            float m[3]; int kk = 0;
#pragma unroll
            for (int j = 0; j < 8; j++) {
                int bq = 0; float bv = vh[0];
#pragma unroll
                for (int q = 1; q < 8; q++)
                    if (vh[q] > bv) { bv = vh[q]; bq = q; }   // tie -> lower eighth
                int ix = 0;
#pragma unroll
                for (int q = 0; q < 8; q++) {
                    if (bq == q) {
                        ix = sAi[(goff + q * 32 + lane) * 8 + pp[q]];
                        pp[q]++;
                        vh[q] = (pp[q] < 8) ? sAv[(goff + q * 32 + lane) * 8 + pp[q]] : -FLT_MAX;
                    }
                }
                cE += sE[ix]; cX += sX[ix]; cY += sY[ix]; cZ += sZ[ix];
                if (j == 1 || j == 3 || j == 7) {
                    float m2 = fmaf(cE, cE, -fmaf(cX, cX, fmaf(cY, cY, cZ * cZ)));
                    m[kk++] = sqrtf(fmaxf(m2, 0.f) + 1e-8f);
                }
            }
            sM[(tg * 32 + lane) * 3 + 0] = m[0];
            sM[(tg * 32 + lane) * 3 + 1] = m[1];
            sM[(tg * 32 + lane) * 3 + 2] = m[2];
        }
    }
    __syncthreads();

    // ---- fused h: 512 threads = 64 tokens x 8 hidden-chunks ----
    {
        int tt = tid >> 3;
        int hh = (tid & 7) * 8;
        float m0 = sM[tt * 3 + 0];
        float m1 = sM[tt * 3 + 1];
        float m2 = sM[tt * 3 + 2];
        emit_h_chunk(b * T_ + tbase0 + tt, hh, m0, m1, m2, sW1s, sb1s);
    }
}

// =========================================================================
// Kernel 3: out = h @ W2 + b2 via mma.sync (fp16, A split 2 terms).
// Block = 256 thr (8 warps): 128 tokens x 64 cols; warp = 32 tok x 32 col.
// =========================================================================
__global__ __launch_bounds__(256) void mlp_mma(
    const float* __restrict__ b2, float* __restrict__ out)
{
    extern __shared__ __align__(1024) unsigned char sm[];
    unsigned char* sAhi = sm;                  // 16K
    unsigned char* sAlo = sm + 16384;          // 16K
    unsigned char* sB   = sm + 32768;          // 8K  (total 40K)

    int tid = threadIdx.x, lane = tid & 31, w = tid >> 5;
    int cb = (blockIdx.x & 7) * 64;
    int tok0 = (blockIdx.x >> 3) * 128;
    int wm = w & 3, wn = w >> 2;
    int qid = lane & 3, grp = lane >> 2;
    int rl = lane & 15, cl = lane >> 4;

#pragma unroll
    for (int i = 0; i < 4; i++) {
        int idx = i * 256 + tid;
        int row = idx >> 3, c = idx & 7;
        uint32_t o = SWZ((uint32_t)(row * 128 + c * 16));
        *(uint4*)(sAhi + o) = ((const uint4*)(g_Ahi + (size_t)(tok0 + row) * H_))[c];
        *(uint4*)(sAlo + o) = ((const uint4*)(g_Alo + (size_t)(tok0 + row) * H_))[c];
    }
#pragma unroll
    for (int i = 0; i < 2; i++) {
        int idx = i * 256 + tid;
        int row = idx >> 3, c = idx & 7;
        uint32_t o = SWZ((uint32_t)(row * 128 + c * 16));
        *(uint4*)(sB + o) = ((const uint4*)(g_Bh + (size_t)(cb + row) * H_))[c];
    }
    __syncthreads();

    uint32_t aAhi = smem_u32(sAhi), aAlo = smem_u32(sAlo);
    uint32_t aB = smem_u32(sB);

    float acc[2][4][4];
#pragma unroll
    for (int nt = 0; nt < 4; nt++) {
        float2 bv = *(const float2*)&b2[cb + wn * 32 + nt * 8 + qid * 2];
#pragma unroll
        for (int mt = 0; mt < 2; mt++) {
            acc[mt][nt][0] = bv.x; acc[mt][nt][1] = bv.y;
            acc[mt][nt][2] = bv.x; acc[mt][nt][3] = bv.y;
        }
    }

#pragma unroll
    for (int ks = 0; ks < 4; ks++) {
        uint32_t ah[2][4], al[2][4];
#pragma unroll
        for (int mt = 0; mt < 2; mt++) {
            uint32_t o = SWZ((uint32_t)((wm * 32 + mt * 16 + rl) * 128 + (ks * 2 + cl) * 16));
            ldm_x4(ah[mt], aAhi + o);
            ldm_x4(al[mt], aAlo + o);
        }
#pragma unroll
        for (int ntp = 0; ntp < 2; ntp++) {
            uint32_t bb[4];
            uint32_t ob = SWZ((uint32_t)((wn * 32 + ntp * 16 + rl) * 128 + (ks * 2 + cl) * 16));
            ldm_x4(bb, aB + ob);
            uint32_t bf0[2] = {bb[0], bb[2]}, bf1[2] = {bb[1], bb[3]};
#pragma unroll
            for (int mt = 0; mt < 2; mt++) {
                MMA16816F(acc[mt][ntp * 2],     ah[mt], bf0);
                MMA16816F(acc[mt][ntp * 2],     al[mt], bf0);
                MMA16816F(acc[mt][ntp * 2 + 1], ah[mt], bf1);
                MMA16816F(acc[mt][ntp * 2 + 1], al[mt], bf1);
            }
        }
    }

#pragma unroll
    for (int mt = 0; mt < 2; mt++) {
        int row = tok0 + wm * 32 + mt * 16 + grp;
#pragma unroll
        for (int nt = 0; nt < 4; nt++) {
            int c = cb + wn * 32 + nt * 8 + qid * 2;
            *(float2*)&out[(size_t)row * D_ + c] =
                make_float2(acc[mt][nt][0], acc[mt][nt][1]);
            *(float2*)&out[(size_t)(row + 8) * D_ + c] =
                make_float2(acc[mt][nt][2], acc[mt][nt][3]);
        }
    }
}

// =========================================================================
extern "C" void kernel_launch(void* const* d_in, const int* in_sizes, int n_in,
                              void* d_out, int out_size)
{
    const float* tokens        = (const float*)d_in[0];
    const unsigned char* mask  = (const unsigned char*)d_in[1];
    const float* W1            = (const float*)d_in[2];
    const float* b1            = (const float*)d_in[3];
    const float* W2            = (const float*)d_in[4];
    const float* b2            = (const float*)d_in[5];
    float* out                 = (float*)d_out;

    const int massSmem = (4 * T_ + 3 * 512 * 8) * 4;   // 81920 bytes
    cudaFuncSetAttribute(mass_kernel,
                         cudaFuncAttributeMaxDynamicSharedMemorySize, massSmem);
    cudaFuncSetAttribute(mlp_mma,
                         cudaFuncAttributeMaxDynamicSharedMemorySize, 40960);

    setup_kernel<<<208, 256>>>(tokens, mask, W2);
    mass_kernel<<<dim3(T_ / 64, B_), 512, massSmem>>>(W1, b1);
    mlp_mma<<<(B_ * T_ / 128) * 8, 256, 40960>>>(b2, out);
}

// round 17
// speedup vs baseline: 1.1406x; 1.0532x over previous
#include <cuda_runtime.h>
#include <cuda_fp16.h>
#include <math.h>
#include <stdint.h>
#include <float.h>

#define B_ 16
#define T_ 2048
#define D_ 512
#define H_ 64

typedef unsigned long long u64;

// ---------------- device scratch (no allocations allowed) ----------------
__device__ float4 g_P[B_ * T_];                    // 4-momenta
__device__ int    g_len[B_];                       // valid lengths per batch
__device__ __half g_Ah[B_ * T_ * H_];              // h (fp16)
__device__ __half g_Bh[D_ * H_];                   // W2^T fp16  [n][k]

// ---------------- f32x2 packed helpers ----------------
__device__ __forceinline__ u64 dup2(float a) {
    u64 r; asm("mov.b64 %0, {%1, %1};" : "=l"(r) : "f"(a)); return r;
}
__device__ __forceinline__ float2 unpack2(u64 v) {
    float2 f; asm("mov.b64 {%0, %1}, %2;" : "=f"(f.x), "=f"(f.y) : "l"(v)); return f;
}
__device__ __forceinline__ u64 fma2(u64 a, u64 b, u64 c) {
    u64 d; asm("fma.rn.f32x2 %0, %1, %2, %3;" : "=l"(d) : "l"(a), "l"(b), "l"(c)); return d;
}
__device__ __forceinline__ u64 mul2(u64 a, u64 b) {
    u64 d; asm("mul.rn.f32x2 %0, %1, %2;" : "=l"(d) : "l"(a), "l"(b)); return d;
}
__device__ __forceinline__ float gelu(float x) {
    return 0.5f * x * (1.f + erff(x * 0.70710678118654752f));
}
__device__ __forceinline__ uint32_t smem_u32(const void* p) {
    uint32_t a;
    asm("{ .reg .u64 t; cvta.to.shared.u64 t, %1; cvt.u32.u64 %0, t; }"
        : "=r"(a) : "l"(p));
    return a;
}

// fp16 mma m16n8k16, f32 accum
#define MMA16816F(d, a, b) \
    asm volatile("mma.sync.aligned.m16n8k16.row.col.f32.f16.f16.f32 " \
        "{%0,%1,%2,%3}, {%4,%5,%6,%7}, {%8,%9}, {%0,%1,%2,%3};" \
        : "+f"((d)[0]), "+f"((d)[1]), "+f"((d)[2]), "+f"((d)[3]) \
        : "r"((a)[0]), "r"((a)[1]), "r"((a)[2]), "r"((a)[3]), \
          "r"((b)[0]), "r"((b)[1]))

__device__ __forceinline__ void ldm_x4(uint32_t* r, uint32_t saddr) {
    asm volatile("ldmatrix.sync.aligned.m8n8.x4.shared.b16 {%0,%1,%2,%3}, [%4];"
        : "=r"(r[0]), "=r"(r[1]), "=r"(r[2]), "=r"(r[3]) : "r"(saddr));
}

#define SWZ(o) ((o) ^ (((o) >> 3) & 0x70))

// =========================================================================
// Kernel 0: fused setup (prep / len / w2t by block range).
// =========================================================================
__global__ __launch_bounds__(256) void setup_kernel(
    const float* __restrict__ tokens, const unsigned char* __restrict__ mask,
    const float* __restrict__ W2)
{
    int bid = blockIdx.x;
    int tid = threadIdx.x;

    if (bid < 64) {
        int gt0 = bid * 512 + tid;
        int gt1 = gt0 + 256;
        float4 tk0 = ((const float4*)tokens)[gt0];
        float4 tk1 = ((const float4*)tokens)[gt1];
        float e0 = fminf(fmaxf(tk0.z, -20.f), 20.f);
        float e1 = fminf(fmaxf(tk1.z, -20.f), 20.f);
        float sp0, cp0, sp1, cp1;
        sincosf(tk0.w, &sp0, &cp0);
        sincosf(tk1.w, &sp1, &cp1);
        float sh0 = sinhf(e0);
        float sh1 = sinhf(e1);
        g_P[gt0] = make_float4(tk0.x, tk0.y * cp0, tk0.y * sp0, tk0.y * sh0);
        g_P[gt1] = make_float4(tk1.x, tk1.y * cp1, tk1.y * sp1, tk1.y * sh1);
    } else if (bid < 80) {
        int b = bid - 64;
        unsigned int w0 = *(const unsigned int*)mask;
        bool byteMode = (w0 == 0x01010101u);
        int cnt = 0;
        for (int s = tid; s < T_; s += 256) {
            unsigned int mv = byteMode ? (unsigned int)mask[b * T_ + s]
                                       : ((const unsigned int*)mask)[b * T_ + s];
            cnt += (mv != 0u);
        }
        for (int o = 16; o; o >>= 1) cnt += __shfl_down_sync(0xffffffffu, cnt, o);
        __shared__ int sred[8];
        if ((tid & 31) == 0) sred[tid >> 5] = cnt;
        __syncthreads();
        if (tid == 0) {
            int tot = 0;
#pragma unroll
            for (int i = 0; i < 8; i++) tot += sred[i];
            g_len[b] = tot;
        }
    } else {
        int idx = (bid - 80) * 256 + tid;
        int k = idx >> 9;
        int n = idx & 511;
        g_Bh[n * H_ + k] = __float2half(W2[k * D_ + n]);
    }
}

// =========================================================================
// Kernel 2: per-token top-8 Minkowski dot -> masses -> FUSED h (fp16).
// Block = 512 threads = 64 tokens: 16 warps = 2 token-groups x 8 eighths.
// =========================================================================
#define CEA(a, b) do { float _l = fminf(a, b), _h = fmaxf(a, b); (a) = _l; (b) = _h; } while (0)

#define SORT8A(v0,v1,v2,v3,v4,v5,v6,v7) do {                 \
    CEA(v0, v1); CEA(v2, v3); CEA(v4, v5); CEA(v6, v7);      \
    CEA(v0, v2); CEA(v1, v3); CEA(v4, v6); CEA(v5, v7);      \
    CEA(v1, v2); CEA(v5, v6);                                \
    CEA(v0, v4); CEA(v1, v5); CEA(v2, v6); CEA(v3, v7);      \
    CEA(v2, v4); CEA(v3, v5);                                \
    CEA(v1, v2); CEA(v3, v4); CEA(v5, v6);                   \
} while (0)

#define CLEAN8(m0,m1,m2,m3,m4,m5,m6,m7) do {                 \
    CEA(m0, m4); CEA(m1, m5); CEA(m2, m6); CEA(m3, m7);      \
    CEA(m0, m2); CEA(m1, m3); CEA(m4, m6); CEA(m5, m7);      \
    CEA(m0, m1); CEA(m2, m3); CEA(m4, m5); CEA(m6, m7);      \
} while (0)

#define VINS(dv) do { float c = (dv), t_;                 \
    t_ = fminf(c, th1); c = fmaxf(c, th1); th0 = t_;      \
    t_ = fminf(c, th2); c = fmaxf(c, th2); th1 = t_;      \
    t_ = fminf(c, th3); c = fmaxf(c, th3); th2 = t_;      \
    t_ = fminf(c, th4); c = fmaxf(c, th4); th3 = t_;      \
    t_ = fminf(c, th5); c = fmaxf(c, th5); th4 = t_;      \
    t_ = fminf(c, th6); c = fmaxf(c, th6); th5 = t_;      \
    t_ = fminf(c, th7); c = fmaxf(c, th7); th6 = t_;      \
    th7 = c;                                              \
} while (0)

#define CAPTURE(dv, si) do {                                          \
    float _d = (dv);                                                  \
    if (_d >= th) {                                                   \
        if (_d > th) {                                                \
            if (na < 8) { av[na] = _d; ai[na] = (si); na++; }         \
        } else {                                                      \
            if (nb < 8) { bi[nb] = (si); nb++; }                      \
        }                                                             \
    }                                                                 \
} while (0)

__device__ __forceinline__ void dot8f(
    const float* sE, const float* sX, const float* sY, const float* sZ,
    int s, u64 aE2, u64 ax2, u64 ay2, u64 az2, float* v)
{
    ulonglong2 E01 = *(const ulonglong2*)&sE[s];
    ulonglong2 X01 = *(const ulonglong2*)&sX[s];
    ulonglong2 Y01 = *(const ulonglong2*)&sY[s];
    ulonglong2 Z01 = *(const ulonglong2*)&sZ[s];
    u64 p0 = fma2(aE2, E01.x, fma2(ax2, X01.x, fma2(ay2, Y01.x, mul2(az2, Z01.x))));
    u64 p1 = fma2(aE2, E01.y, fma2(ax2, X01.y, fma2(ay2, Y01.y, mul2(az2, Z01.y))));
    float2 d0 = unpack2(p0), d1 = unpack2(p1);
    v[0] = d0.x; v[1] = d0.y; v[2] = d1.x; v[3] = d1.y;
}

// per-thread h-chunk: token gt (global), hidden [hh, hh+8) -> fp16
__device__ __forceinline__ void emit_h_chunk(
    int gt, int hh, float m0, float m1, float m2,
    const float* sW1s, const float* sb1s)
{
    __align__(16) __half h8[8];
#pragma unroll
    for (int j = 0; j < 8; j++) {
        int k = hh + j;
        float x = fmaf(m0, sW1s[k], fmaf(m1, sW1s[H_ + k],
                  fmaf(m2, sW1s[2 * H_ + k], sb1s[k])));
        h8[j] = __float2half(gelu(x));
    }
    *(uint4*)&g_Ah[(size_t)gt * H_ + hh] = *(const uint4*)h8;
}

__global__ __launch_bounds__(512) void mass_kernel(
    const float* __restrict__ W1, const float* __restrict__ b1)
{
    extern __shared__ __align__(16) unsigned char smem_raw[];
    float* sE  = (float*)smem_raw;
    float* sX  = sE + T_;
    float* sY  = sX + T_;
    float* sZ  = sY + T_;
    float* sAv = sZ + T_;                     // [512*8]
    int*   sAi = (int*)(sAv + 512 * 8);       // [512*8]
    int*   sBi = sAi + 512 * 8;               // [512*8]
    __shared__ float sM[64 * 3];
    __shared__ float sW1s[3 * H_];
    __shared__ float sb1s[H_];

    int b = blockIdx.y;
    int len = g_len[b];
    int tbase0 = blockIdx.x * 64;
    int tid = threadIdx.x, lane = tid & 31, w = tid >> 5;
    int tg = w >> 3, we = w & 7;
    float mv = sqrtf(1e-8f);

    if (tid < 3 * H_) sW1s[tid] = W1[tid];
    if (tid < H_) sb1s[tid] = b1[tid];

    if (tbase0 >= len) {                 // whole 64-token block masked
        __syncthreads();
        int tt = tid >> 3;
        int hh = (tid & 7) * 8;
        emit_h_chunk(b * T_ + tbase0 + tt, hh, mv, mv, mv, sW1s, sb1s);
        return;
    }

    const float4* gp = g_P + b * T_;
    for (int i = tid; i < T_; i += 512) {
        float4 p = gp[i];
        sE[i] = p.x; sX[i] = p.y; sY[i] = p.z; sZ[i] = p.w;
    }
    __syncthreads();

    int t = tbase0 + tg * 32 + lane;
    int q0 = (we * len) >> 3;
    int q1 = ((we + 1) * len) >> 3;

    float aE = sE[t], ax = -sX[t], ay = -sY[t], az = -sZ[t];
    u64 aE2 = dup2(aE), ax2 = dup2(ax), ay2 = dup2(ay), az2 = dup2(az);

    float th0 = -FLT_MAX, th1 = -FLT_MAX, th2 = -FLT_MAX, th3 = -FLT_MAX;
    float th4 = -FLT_MAX, th5 = -FLT_MAX, th6 = -FLT_MAX, th7 = -FLT_MAX;

    int s0 = (q0 + 3) & ~3; if (s0 > q1) s0 = q1;
    int s1a = s0 + ((q1 - s0) & ~15);

    // ---- pass 1: always-sort batched top-8 (value-multiset exact) ----
    for (int s = q0; s < s0; s++) {
        float d = fmaf(aE, sE[s], fmaf(ax, sX[s], fmaf(ay, sY[s], az * sZ[s])));
        if (d > th0) VINS(d);
    }
    for (int s = s0; s < s1a; s += 16) {
        float v[16];
        dot8f(sE, sX, sY, sZ, s,      aE2, ax2, ay2, az2, v);
        dot8f(sE, sX, sY, sZ, s + 4,  aE2, ax2, ay2, az2, v + 4);
        dot8f(sE, sX, sY, sZ, s + 8,  aE2, ax2, ay2, az2, v + 8);
        dot8f(sE, sX, sY, sZ, s + 12, aE2, ax2, ay2, az2, v + 12);
        SORT8A(v[0], v[1], v[2], v[3], v[4], v[5], v[6], v[7]);
        SORT8A(v[8], v[9], v[10], v[11], v[12], v[13], v[14], v[15]);
        float m0 = fmaxf(v[0], v[15]), m1 = fmaxf(v[1], v[14]);
        float m2 = fmaxf(v[2], v[13]), m3 = fmaxf(v[3], v[12]);
        float m4 = fmaxf(v[4], v[11]), m5 = fmaxf(v[5], v[10]);
        float m6 = fmaxf(v[6], v[9]),  m7 = fmaxf(v[7], v[8]);
        CLEAN8(m0, m1, m2, m3, m4, m5, m6, m7);
        float u0 = fmaxf(th0, m7), u1 = fmaxf(th1, m6);
        float u2 = fmaxf(th2, m5), u3 = fmaxf(th3, m4);
        float u4 = fmaxf(th4, m3), u5 = fmaxf(th5, m2);
        float u6 = fmaxf(th6, m1), u7 = fmaxf(th7, m0);
        CLEAN8(u0, u1, u2, u3, u4, u5, u6, u7);
        th0 = u0; th1 = u1; th2 = u2; th3 = u3;
        th4 = u4; th5 = u5; th6 = u6; th7 = u7;
    }
    for (int s = s1a; s < q1; s++) {
        float d = fmaf(aE, sE[s], fmaf(ax, sX[s], fmaf(ay, sY[s], az * sZ[s])));
        if (d > th0) VINS(d);
    }

    // ---- pass 2: tie-exact index capture in ascending s ----
    float th = th0;
    float* av = &sAv[tid * 8];
    int*   ai = &sAi[tid * 8];
    int*   bi = &sBi[tid * 8];
    int na = 0, nb = 0;

    for (int s = q0; s < s0; s++) {
        float d = fmaf(aE, sE[s], fmaf(ax, sX[s], fmaf(ay, sY[s], az * sZ[s])));
        CAPTURE(d, s);
    }
    for (int s = s0; s < s1a; s += 16) {
        float v[16];
        dot8f(sE, sX, sY, sZ, s,      aE2, ax2, ay2, az2, v);
        dot8f(sE, sX, sY, sZ, s + 4,  aE2, ax2, ay2, az2, v + 4);
        dot8f(sE, sX, sY, sZ, s + 8,  aE2, ax2, ay2, az2, v + 8);
        dot8f(sE, sX, sY, sZ, s + 12, aE2, ax2, ay2, az2, v + 12);
        float g0 = fmaxf(fmaxf(v[0], v[1]), fmaxf(v[2], v[3]));
        float g1 = fmaxf(fmaxf(v[4], v[5]), fmaxf(v[6], v[7]));
        float g2 = fmaxf(fmaxf(v[8], v[9]), fmaxf(v[10], v[11]));
        float g3 = fmaxf(fmaxf(v[12], v[13]), fmaxf(v[14], v[15]));
        if (fmaxf(fmaxf(g0, g1), fmaxf(g2, g3)) >= th) {
#pragma unroll
            for (int k = 0; k < 16; k++) CAPTURE(v[k], s + k);
        }
    }
    for (int s = s1a; s < q1; s++) {
        float d = fmaf(aE, sE[s], fmaf(ax, sX[s], fmaf(ay, sY[s], az * sZ[s])));
        CAPTURE(d, s);
    }

    // ---- build eighth list: stable-desc-sort(A) ++ ties(B asc index) ----
    {
        float v[8]; int idA[8]; int bReg[8];
#pragma unroll
        for (int j = 0; j < 8; j++) {
            v[j]   = (j < na) ? av[j] : -FLT_MAX;
            idA[j] = (j < na) ? ai[j] : 0;
            bReg[j] = bi[j];
        }
#pragma unroll
        for (int i = 0; i < 7; i++) {
#pragma unroll
            for (int j = 0; j < 7 - i; j++) {
                bool p = v[j + 1] > v[j];
                float hv = p ? v[j + 1] : v[j];
                float lv = p ? v[j] : v[j + 1];
                int hi_ = p ? idA[j + 1] : idA[j];
                int lo_ = p ? idA[j] : idA[j + 1];
                v[j] = hv; v[j + 1] = lv; idA[j] = hi_; idA[j + 1] = lo_;
            }
        }
#pragma unroll
        for (int j = 0; j < 8; j++) {
            int jb = j - na; jb = jb < 0 ? 0 : (jb > 7 ? 7 : jb);
            av[j] = (j < na) ? v[j] : th;
            ai[j] = (j < na) ? idA[j] : bReg[jb];
        }
    }
    __syncthreads();

    // ---- warps 0 and 8: 8-way merge + cumsum for their token group ----
    if (we == 0) {
        int goff = tg * 256;
        int tt = tbase0 + tg * 32 + lane;
        if (tt >= len) {
            sM[(tg * 32 + lane) * 3 + 0] = mv;
            sM[(tg * 32 + lane) * 3 + 1] = mv;
            sM[(tg * 32 + lane) * 3 + 2] = mv;
        } else {
            float vh[8]; int pp[8];
#pragma unroll
            for (int q = 0; q < 8; q++) {
                pp[q] = 0;
                vh[q] = sAv[(goff + q * 32 + lane) * 8];
            }
            float cE = 0.f, cX = 0.f, cY = 0.f, cZ = 0.f;
            float m[3]; int kk = 0;
#pragma unroll
            for (int j = 0; j < 8; j++) {
                int bq = 0; float bv = vh[0];
#pragma unroll
                for (int q = 1; q < 8; q++)
                    if (vh[q] > bv) { bv = vh[q]; bq = q; }   // tie -> lower eighth
                int ix = 0;
#pragma unroll
                for (int q = 0; q < 8; q++) {
                    if (bq == q) {
                        ix = sAi[(goff + q * 32 + lane) * 8 + pp[q]];
                        pp[q]++;
                        vh[q] = (pp[q] < 8) ? sAv[(goff + q * 32 + lane) * 8 + pp[q]] : -FLT_MAX;
                    }
                }
                cE += sE[ix]; cX += sX[ix]; cY += sY[ix]; cZ += sZ[ix];
                if (j == 1 || j == 3 || j == 7) {
                    float m2 = fmaf(cE, cE, -fmaf(cX, cX, fmaf(cY, cY, cZ * cZ)));
                    m[kk++] = sqrtf(fmaxf(m2, 0.f) + 1e-8f);
                }
            }
            sM[(tg * 32 + lane) * 3 + 0] = m[0];
            sM[(tg * 32 + lane) * 3 + 1] = m[1];
            sM[(tg * 32 + lane) * 3 + 2] = m[2];
        }
    }
    __syncthreads();

    // ---- fused h: 512 threads = 64 tokens x 8 hidden-chunks ----
    {
        int tt = tid >> 3;
        int hh = (tid & 7) * 8;
        float m0 = sM[tt * 3 + 0];
        float m1 = sM[tt * 3 + 1];
        float m2 = sM[tt * 3 + 2];
        emit_h_chunk(b * T_ + tbase0 + tt, hh, m0, m1, m2, sW1s, sb1s);
    }
}

// =========================================================================
// Kernel 3: out = h @ W2 + b2 via mma.sync (fp16 single term).
// Block = 256 thr (8 warps): 128 tokens x 64 cols; warp = 32 tok x 32 col.
// Smem 24 KB -> higher blocks/SM.
// =========================================================================
__global__ __launch_bounds__(256) void mlp_mma(
    const float* __restrict__ b2, float* __restrict__ out)
{
    extern __shared__ __align__(1024) unsigned char sm[];
    unsigned char* sA = sm;                    // 128 x 128B = 16K
    unsigned char* sB = sm + 16384;            // 64 x 128B = 8K  (total 24K)

    int tid = threadIdx.x, lane = tid & 31, w = tid >> 5;
    int cb = (blockIdx.x & 7) * 64;
    int tok0 = (blockIdx.x >> 3) * 128;
    int wm = w & 3, wn = w >> 2;
    int qid = lane & 3, grp = lane >> 2;
    int rl = lane & 15, cl = lane >> 4;

#pragma unroll
    for (int i = 0; i < 4; i++) {
        int idx = i * 256 + tid;
        int row = idx >> 3, c = idx & 7;
        uint32_t o = SWZ((uint32_t)(row * 128 + c * 16));
        *(uint4*)(sA + o) = ((const uint4*)(g_Ah + (size_t)(tok0 + row) * H_))[c];
    }
#pragma unroll
    for (int i = 0; i < 2; i++) {
        int idx = i * 256 + tid;
        int row = idx >> 3, c = idx & 7;
        uint32_t o = SWZ((uint32_t)(row * 128 + c * 16));
        *(uint4*)(sB + o) = ((const uint4*)(g_Bh + (size_t)(cb + row) * H_))[c];
    }
    __syncthreads();

    uint32_t aA = smem_u32(sA);
    uint32_t aB = smem_u32(sB);

    float acc[2][4][4];
#pragma unroll
    for (int nt = 0; nt < 4; nt++) {
        float2 bv = *(const float2*)&b2[cb + wn * 32 + nt * 8 + qid * 2];
#pragma unroll
        for (int mt = 0; mt < 2; mt++) {
            acc[mt][nt][0] = bv.x; acc[mt][nt][1] = bv.y;
            acc[mt][nt][2] = bv.x; acc[mt][nt][3] = bv.y;
        }
    }

#pragma unroll
    for (int ks = 0; ks < 4; ks++) {
        uint32_t ah[2][4];
#pragma unroll
        for (int mt = 0; mt < 2; mt++) {
            uint32_t o = SWZ((uint32_t)((wm * 32 + mt * 16 + rl) * 128 + (ks * 2 + cl) * 16));
            ldm_x4(ah[mt], aA + o);
        }
#pragma unroll
        for (int ntp = 0; ntp < 2; ntp++) {
            uint32_t bb[4];
            uint32_t ob = SWZ((uint32_t)((wn * 32 + ntp * 16 + rl) * 128 + (ks * 2 + cl) * 16));
            ldm_x4(bb, aB + ob);
            uint32_t bf0[2] = {bb[0], bb[2]}, bf1[2] = {bb[1], bb[3]};
#pragma unroll
            for (int mt = 0; mt < 2; mt++) {
                MMA16816F(acc[mt][ntp * 2],     ah[mt], bf0);
                MMA16816F(acc[mt][ntp * 2 + 1], ah[mt], bf1);
            }
        }
    }

#pragma unroll
    for (int mt = 0; mt < 2; mt++) {
        int row = tok0 + wm * 32 + mt * 16 + grp;
#pragma unroll
        for (int nt = 0; nt < 4; nt++) {
            int c = cb + wn * 32 + nt * 8 + qid * 2;
            *(float2*)&out[(size_t)row * D_ + c] =
                make_float2(acc[mt][nt][0], acc[mt][nt][1]);
            *(float2*)&out[(size_t)(row + 8) * D_ + c] =
                make_float2(acc[mt][nt][2], acc[mt][nt][3]);
        }
    }
}

// =========================================================================
extern "C" void kernel_launch(void* const* d_in, const int* in_sizes, int n_in,
                              void* d_out, int out_size)
{
    const float* tokens        = (const float*)d_in[0];
    const unsigned char* mask  = (const unsigned char*)d_in[1];
    const float* W1            = (const float*)d_in[2];
    const float* b1            = (const float*)d_in[3];
    const float* W2            = (const float*)d_in[4];
    const float* b2            = (const float*)d_in[5];
    float* out                 = (float*)d_out;

    const int massSmem = (4 * T_ + 3 * 512 * 8) * 4;   // 81920 bytes
    cudaFuncSetAttribute(mass_kernel,
                         cudaFuncAttributeMaxDynamicSharedMemorySize, massSmem);
    cudaFuncSetAttribute(mlp_mma,
                         cudaFuncAttributeMaxDynamicSharedMemorySize, 24576);

    setup_kernel<<<208, 256>>>(tokens, mask, W2);
    mass_kernel<<<dim3(T_ / 64, B_), 512, massSmem>>>(W1, b1);
    mlp_mma<<<(B_ * T_ / 128) * 8, 256, 24576>>>(b2, out);
}